// round 1
// baseline (speedup 1.0000x reference)
#include <cuda_runtime.h>
#include <math.h>
#include <stdint.h>

// ---------------------------------------------------------------------------
// GFASTKAN: 3x (FastKAN layer -> GCN aggregate)
//   N=100000 nodes, F=128, H=128, C=47, E=1600000 edges, G=4 RBF grids
//   grid = linspace(-2,2,4) = {-2, -2/3, 2/3, 2}; denom = 4/3 -> inv = 0.75
// ---------------------------------------------------------------------------

#define NN 100000
#define FEAT 128

// scratch (device globals; allocation-free per harness rules)
__device__ float g_deg[NN];            // degree -> dinv (in place)
__device__ float g_t[NN * 128];        // FKAN output (pre-aggregation), reused
__device__ float g_h1[NN * 128];       // layer-1 aggregated output (kept for cat)
__device__ float g_h2[NN * 128];       // layer-2 aggregated output (kept for cat)

// ---------------------------------------------------------------------------
// degree / normalization kernels
// ---------------------------------------------------------------------------
__global__ void deg_init_kernel(float* deg, int n) {
    int i = blockIdx.x * blockDim.x + threadIdx.x;
    if (i < n) deg[i] = 1.0f;          // self-loop contributes 1
}

__global__ void deg_count_kernel(const int* __restrict__ dst, float* deg, int E) {
    int e = blockIdx.x * blockDim.x + threadIdx.x;
    if (e < E) atomicAdd(&deg[dst[e]], 1.0f);
}

__global__ void dinv_kernel(float* deg, int n) {
    int i = blockIdx.x * blockDim.x + threadIdx.x;
    if (i < n) deg[i] = rsqrtf(deg[i]);   // deg >= 1 always (self loops)
}

// ---------------------------------------------------------------------------
// Fused FastKAN layer:
//   out[r][o] = sum_d sum_g exp(-((z[r][d]-grid_g)*0.75)^2) * Ws[o][d*4+g]
//             + sum_d silu(x[r][d]) * Wb[o][d]  + bs[o] + bb[o]
//   z = LayerNorm(x) * gamma + beta
// Layer 2 input is the concatenation [x | h1 | h2] (DIN=384), passed as X0..X2.
// ---------------------------------------------------------------------------
template <int DIN>
__device__ __forceinline__ float loadX(const float* __restrict__ X0,
                                       const float* __restrict__ X1,
                                       const float* __restrict__ X2,
                                       int r, int d) {
    if constexpr (DIN == 384) {
        if (d < 128)      return X0[(size_t)r * 128 + d];
        else if (d < 256) return X1[(size_t)r * 128 + (d - 128)];
        else              return X2[(size_t)r * 128 + (d - 256)];
    } else {
        return X0[(size_t)r * DIN + d];
    }
}

template <int DIN, int DOUT, int BN, int TM, int TN, int DC>
__global__ __launch_bounds__(128)
void fkan_kernel(const float* __restrict__ X0, const float* __restrict__ X1,
                 const float* __restrict__ X2,
                 const float* __restrict__ gam, const float* __restrict__ bet,
                 const float* __restrict__ Ws,  const float* __restrict__ bs,
                 const float* __restrict__ Wb,  const float* __restrict__ bb,
                 float* __restrict__ out, int nrows) {
    constexpr int BM  = 64;
    constexpr int KC  = DC * 5;                 // DC*4 rbf rows + DC silu rows
    constexpr int BNP = BN + 1;                 // odd stride -> conflict-free W stores
    constexpr int NT  = (BM / TM) * (BN / TN);  // 128 threads
    static_assert(NT == 128, "thread count must be 128");

    __shared__ float sMu[BM], sRs[BM];
    __shared__ float sG[DIN], sB[DIN];
    __shared__ float sA[KC][BM];
    __shared__ float sW[KC][BNP];

    const int t    = threadIdx.x;
    const int row0 = blockIdx.x * BM;
    const int lane = t & 31;
    const int warp = t >> 5;

    // preload gamma/beta
    for (int i = t; i < DIN; i += NT) { sG[i] = gam[i]; sB[i] = bet[i]; }

    // layernorm stats: one warp per node
    for (int n = warp; n < BM; n += NT / 32) {
        int r = row0 + n;
        float s = 0.f, ss = 0.f;
        if (r < nrows) {
            for (int d = lane; d < DIN; d += 32) {
                float v = loadX<DIN>(X0, X1, X2, r, d);
                s += v; ss += v * v;
            }
        }
        #pragma unroll
        for (int off = 16; off; off >>= 1) {
            s  += __shfl_xor_sync(0xffffffffu, s,  off);
            ss += __shfl_xor_sync(0xffffffffu, ss, off);
        }
        if (lane == 0) {
            float mu  = s * (1.0f / DIN);
            float var = ss * (1.0f / DIN) - mu * mu;
            sMu[n] = mu;
            sRs[n] = rsqrtf(var + 1e-5f);
        }
    }
    __syncthreads();

    float acc[TM][TN];
    #pragma unroll
    for (int i = 0; i < TM; i++)
        #pragma unroll
        for (int j = 0; j < TN; j++) acc[i][j] = 0.f;

    const int cgrp = t % (BN / TN);  // column group (0..15)
    const int rgrp = t / (BN / TN);  // row group    (0..7)

    const float GR0 = -2.0f, GR1 = -2.0f / 3.0f, GR2 = 2.0f / 3.0f, GR3 = 2.0f;

    for (int d0 = 0; d0 < DIN; d0 += DC) {
        // build A chunk (k-major): rbf rows [0,4*DC), silu rows [4*DC,5*DC)
        for (int p = t; p < BM * DC; p += NT) {
            int n = p / DC, dd = p % DC;
            int r = row0 + n, d = d0 + dd;
            float x = (r < nrows) ? loadX<DIN>(X0, X1, X2, r, d) : 0.f;
            float z = (x - sMu[n]) * sRs[n] * sG[d] + sB[d];
            float u0 = (z - GR0) * 0.75f;
            float u1 = (z - GR1) * 0.75f;
            float u2 = (z - GR2) * 0.75f;
            float u3 = (z - GR3) * 0.75f;
            sA[dd * 4 + 0][n] = __expf(-u0 * u0);
            sA[dd * 4 + 1][n] = __expf(-u1 * u1);
            sA[dd * 4 + 2][n] = __expf(-u2 * u2);
            sA[dd * 4 + 3][n] = __expf(-u3 * u3);
            sA[DC * 4 + dd][n] = x / (1.0f + __expf(-x));   // silu
        }
        // load Ws chunk (transpose into k-major smem; odd BNP -> conflict-free)
        for (int p = t; p < BN * DC * 4; p += NT) {
            int o = p / (DC * 4), kk = p % (DC * 4);
            float w = (o < DOUT) ? Ws[(size_t)o * (DIN * 4) + d0 * 4 + kk] : 0.f;
            sW[kk][o] = w;
        }
        // load Wb chunk
        for (int p = t; p < BN * DC; p += NT) {
            int o = p / DC, kk = p % DC;
            float w = (o < DOUT) ? Wb[(size_t)o * DIN + d0 + kk] : 0.f;
            sW[DC * 4 + kk][o] = w;
        }
        __syncthreads();

        #pragma unroll 4
        for (int k = 0; k < KC; k++) {
            float a[TM], w[TN];
            #pragma unroll
            for (int i = 0; i < TM; i++) a[i] = sA[k][rgrp + (BM / TM) * i];
            #pragma unroll
            for (int j = 0; j < TN; j++) w[j] = sW[k][cgrp + (BN / TN) * j];
            #pragma unroll
            for (int i = 0; i < TM; i++)
                #pragma unroll
                for (int j = 0; j < TN; j++) acc[i][j] += a[i] * w[j];
        }
        __syncthreads();
    }

    // epilogue: + bs + bb
    #pragma unroll
    for (int i = 0; i < TM; i++) {
        int r = row0 + rgrp + (BM / TM) * i;
        if (r >= nrows) continue;
        #pragma unroll
        for (int j = 0; j < TN; j++) {
            int o = cgrp + (BN / TN) * j;
            if (o < DOUT)
                out[(size_t)r * DOUT + o] = acc[i][j] + bs[o] + bb[o];
        }
    }
}

// ---------------------------------------------------------------------------
// GCN aggregation
// ---------------------------------------------------------------------------
// out[r][f] = t[r][f]*dinv[r]^2 + bg[f]   (self-loop + bias init)
__global__ void agg_init_kernel(const float* __restrict__ tin,
                                const float* __restrict__ dinv,
                                const float* __restrict__ bg,
                                float* __restrict__ out, int n, int F) {
    int idx = blockIdx.x * blockDim.x + threadIdx.x;
    if (idx >= n * F) return;
    int r = idx / F, f = idx - r * F;
    float di = dinv[r];
    out[idx] = tin[idx] * di * di + bg[f];
}

// out[dst][f] += t[src][f] * dinv[src]*dinv[dst]   (warp per edge)
__global__ void agg_edges_kernel(const float* __restrict__ tin,
                                 const int* __restrict__ src,
                                 const int* __restrict__ dst,
                                 const float* __restrict__ dinv,
                                 float* __restrict__ out, int E, int F) {
    int warp = (blockIdx.x * blockDim.x + threadIdx.x) >> 5;
    int lane = threadIdx.x & 31;
    if (warp >= E) return;
    int s = src[warp], d = dst[warp];
    float w = dinv[s] * dinv[d];
    const float* ts = tin + (size_t)s * F;
    float*       od = out + (size_t)d * F;
    for (int f = lane; f < F; f += 32)
        atomicAdd(&od[f], ts[f] * w);
}

// ---------------------------------------------------------------------------
// launch
// ---------------------------------------------------------------------------
extern "C" void kernel_launch(void* const* d_in, const int* in_sizes, int n_in,
                              void* d_out, int out_size) {
    const float* x  = (const float*)d_in[0];
    const int*   ei = (const int*)d_in[1];
    const int N = in_sizes[0] / FEAT;       // 100000
    const int E = in_sizes[1] / 2;          // 1600000
    const int* e_src = ei;
    const int* e_dst = ei + E;

    // params: per layer i -> ln_g, ln_b, Ws, bs, Wb, bb, bg at indices 2+7i..8+7i
    const float* P[21];
    for (int i = 0; i < 21; i++) P[i] = (const float*)d_in[2 + i];

    float *deg, *t, *h1, *h2;
    cudaGetSymbolAddress((void**)&deg, g_deg);
    cudaGetSymbolAddress((void**)&t,   g_t);
    cudaGetSymbolAddress((void**)&h1,  g_h1);
    cudaGetSymbolAddress((void**)&h2,  g_h2);
    float* out = (float*)d_out;

    // degree -> dinv
    deg_init_kernel<<<(N + 255) / 256, 256>>>(deg, N);
    deg_count_kernel<<<(E + 255) / 256, 256>>>(e_dst, deg, E);
    dinv_kernel<<<(N + 255) / 256, 256>>>(deg, N);

    const int GB = (N + 63) / 64;

    // ---- layer 0: x (N,128) -> h1 (N,128)
    fkan_kernel<128, 128, 128, 8, 8, 8><<<GB, 128>>>(
        x, nullptr, nullptr, P[0], P[1], P[2], P[3], P[4], P[5], t, N);
    agg_init_kernel<<<(N * 128 + 255) / 256, 256>>>(t, deg, P[6], h1, N, 128);
    agg_edges_kernel<<<(E * 32 + 255) / 256, 256>>>(t, e_src, e_dst, deg, h1, E, 128);

    // ---- layer 1: h1 (N,128) -> h2 (N,128)
    fkan_kernel<128, 128, 128, 8, 8, 8><<<GB, 128>>>(
        h1, nullptr, nullptr, P[7], P[8], P[9], P[10], P[11], P[12], t, N);
    agg_init_kernel<<<(N * 128 + 255) / 256, 256>>>(t, deg, P[13], h2, N, 128);
    agg_edges_kernel<<<(E * 32 + 255) / 256, 256>>>(t, e_src, e_dst, deg, h2, E, 128);

    // ---- layer 2: [x|h1|h2] (N,384) -> out (N,47)
    fkan_kernel<384, 47, 48, 8, 3, 8><<<GB, 128>>>(
        x, h1, h2, P[14], P[15], P[16], P[17], P[18], P[19], t, N);
    agg_init_kernel<<<(N * 47 + 255) / 256, 256>>>(t, deg, P[20], out, N, 47);
    agg_edges_kernel<<<(E * 32 + 255) / 256, 256>>>(t, e_src, e_dst, deg, out, E, 47);
}

// round 3
// speedup vs baseline: 1.2819x; 1.2819x over previous
#include <cuda_runtime.h>
#include <math.h>
#include <stdint.h>

#define NN 100000
#define FEAT 128

// ---------------- scratch (device globals; allocation-free) ----------------
__device__ __align__(16) float g_deg[NN];
__device__ __align__(16) float g_t[NN * 128];     // FKAN pre-aggregation output
__device__ __align__(16) float g_h1[NN * 128];
__device__ __align__(16) float g_h2[NN * 128];
__device__ __align__(16) float g_pad[NN * 48];    // layer-2 padded aggregate
__device__ __align__(16) float g_wt0[640 * 128];  // combined k-major weights
__device__ __align__(16) float g_wt1[640 * 128];
__device__ __align__(16) float g_wt2[1920 * 48];

// ---------------- degree ----------------
__global__ void deg_init_kernel(float* deg, int n) {
    int i = blockIdx.x * blockDim.x + threadIdx.x;
    if (i < n) deg[i] = 1.0f;
}
__global__ void deg_count_kernel(const int* __restrict__ dst, float* deg, int E) {
    int e = blockIdx.x * blockDim.x + threadIdx.x;
    if (e < E) atomicAdd(&deg[dst[e]], 1.0f);
}
__global__ void dinv_kernel(float* deg, int n) {
    int i = blockIdx.x * blockDim.x + threadIdx.x;
    if (i < n) deg[i] = rsqrtf(deg[i]);
}

// ---------------- weight pre-transpose: Wt[(d*5+g)][o] ----------------
// g in 0..3 -> Ws[o][d*4+g]; g==4 -> Wb[o][d]; zero-pad o >= DOUT
__global__ void wt_kernel(const float* __restrict__ Ws, const float* __restrict__ Wb,
                          float* __restrict__ Wt, int DIN, int DOUT, int BN) {
    int idx = blockIdx.x * blockDim.x + threadIdx.x;
    int tot = DIN * 5 * BN;
    if (idx >= tot) return;
    int k = idx / BN, o = idx - k * BN;
    int d = k / 5, g = k - d * 5;
    float v = 0.f;
    if (o < DOUT) v = (g < 4) ? Ws[(size_t)o * (DIN * 4) + d * 4 + g]
                              : Wb[(size_t)o * DIN + d];
    Wt[idx] = v;
}

// ---------------- input loaders (layer 2 = concat [x|h1|h2]) ----------------
template <int DIN>
__device__ __forceinline__ float4 loadX4(const float* __restrict__ X0,
                                         const float* __restrict__ X1,
                                         const float* __restrict__ X2,
                                         int r, int d) {
    if constexpr (DIN == 384) {
        if (d < 128)      return *(const float4*)(X0 + (size_t)r * 128 + d);
        else if (d < 256) return *(const float4*)(X1 + (size_t)r * 128 + (d - 128));
        else              return *(const float4*)(X2 + (size_t)r * 128 + (d - 256));
    } else {
        return *(const float4*)(X0 + (size_t)r * DIN + d);
    }
}

// ---------------- fused FastKAN layer ----------------
// out_t[r][o]  = acc + bs[o] + bb[o]                         (pre-aggregation)
// out_i[r][o]  = out_t[r][o] * dinv[r]^2 + bg[o]             (self-loop + bias)
template <int DIN, int DOUT, int BN, int TM, int OUTS>
__global__ void __launch_bounds__((128 / TM) * (BN / 8))
fkan2(const float* __restrict__ X0, const float* __restrict__ X1,
      const float* __restrict__ X2,
      const float* __restrict__ gam, const float* __restrict__ bet,
      const float* __restrict__ Wt,  const float* __restrict__ bs,
      const float* __restrict__ bb,  const float* __restrict__ bg,
      const float* __restrict__ dinv,
      float* __restrict__ out_t, float* __restrict__ out_i, int nrows) {
    constexpr int BM = 128;
    constexpr int TN = 8;
    constexpr int DC = 8;
    constexpr int KC = DC * 5;                    // 40 k-rows per chunk
    constexpr int NT = (BM / TM) * (BN / TN);
    static_assert(NT % 32 == 0, "warp multiple");

    __shared__ float sMu[BM], sRs[BM];
    __shared__ float sG[DIN], sB[DIN];
    __shared__ float sA[KC * BM];
    __shared__ float sW[KC * BN];

    const int t    = threadIdx.x;
    const int row0 = blockIdx.x * BM;
    const int lane = t & 31;
    const int warp = t >> 5;
    const int cgrp = t % (BN / TN);
    const int rgrp = t / (BN / TN);

    for (int i = t; i < DIN; i += NT) { sG[i] = gam[i]; sB[i] = bet[i]; }

    // layernorm stats: one warp per node, float4 loads
    for (int n = warp; n < BM; n += NT / 32) {
        int r = row0 + n;
        float s = 0.f, ss = 0.f;
        if (r < nrows) {
            for (int d4 = lane; d4 < DIN / 4; d4 += 32) {
                float4 v = loadX4<DIN>(X0, X1, X2, r, d4 * 4);
                s  += v.x + v.y + v.z + v.w;
                ss += v.x * v.x + v.y * v.y + v.z * v.z + v.w * v.w;
            }
        }
        #pragma unroll
        for (int off = 16; off; off >>= 1) {
            s  += __shfl_xor_sync(0xffffffffu, s,  off);
            ss += __shfl_xor_sync(0xffffffffu, ss, off);
        }
        if (lane == 0) {
            float mu  = s * (1.0f / DIN);
            float var = ss * (1.0f / DIN) - mu * mu;
            sMu[n] = mu;
            sRs[n] = rsqrtf(var + 1e-5f);
        }
    }
    __syncthreads();

    float acc[TM][TN];
    #pragma unroll
    for (int i = 0; i < TM; i++)
        #pragma unroll
        for (int j = 0; j < TN; j++) acc[i][j] = 0.f;

    const float GR[4] = {-2.0f, -2.0f / 3.0f, 2.0f / 3.0f, 2.0f};

    for (int ch = 0; ch < DIN / DC; ch++) {
        const int d0 = ch * DC;
        // ---- build A chunk (k = dd*5 + g; g==4 is silu) ----
        for (int p = t; p < BM * 2; p += NT) {
            int n = p >> 1, q = p & 1;
            int r = row0 + n, d = d0 + q * 4;
            float4 xv = make_float4(0.f, 0.f, 0.f, 0.f);
            if (r < nrows) xv = loadX4<DIN>(X0, X1, X2, r, d);
            float mu = sMu[n], rs = sRs[n];
            float xs[4] = {xv.x, xv.y, xv.z, xv.w};
            #pragma unroll
            for (int j = 0; j < 4; j++) {
                int dd = q * 4 + j;
                float x = xs[j];
                float z = (x - mu) * rs * sG[d0 + dd] + sB[d0 + dd];
                #pragma unroll
                for (int g = 0; g < 4; g++) {
                    float u = (z - GR[g]) * 0.75f;
                    sA[(dd * 5 + g) * BM + n] = __expf(-u * u);
                }
                sA[(dd * 5 + 4) * BM + n] = x / (1.0f + __expf(-x));
            }
        }
        // ---- copy contiguous Wt slab into smem (float4) ----
        {
            const float4* wsrc = (const float4*)(Wt + (size_t)d0 * 5 * BN);
            float4* wdst = (float4*)sW;
            for (int p = t; p < KC * BN / 4; p += NT) wdst[p] = wsrc[p];
        }
        __syncthreads();

        #pragma unroll 4
        for (int k = 0; k < KC; k++) {
            float4 w0 = *(const float4*)&sW[k * BN + cgrp * TN];
            float4 w1 = *(const float4*)&sW[k * BN + cgrp * TN + 4];
            float a[TM];
            *(float4*)&a[0] = *(const float4*)&sA[k * BM + rgrp * TM];
            if constexpr (TM == 8)
                *(float4*)&a[4] = *(const float4*)&sA[k * BM + rgrp * TM + 4];
            #pragma unroll
            for (int i = 0; i < TM; i++) {
                acc[i][0] += a[i] * w0.x;  acc[i][1] += a[i] * w0.y;
                acc[i][2] += a[i] * w0.z;  acc[i][3] += a[i] * w0.w;
                acc[i][4] += a[i] * w1.x;  acc[i][5] += a[i] * w1.y;
                acc[i][6] += a[i] * w1.z;  acc[i][7] += a[i] * w1.w;
            }
        }
        __syncthreads();
    }

    // ---- epilogue: biases, raw t, and fused self-loop init ----
    #pragma unroll
    for (int i = 0; i < TM; i++) {
        int r = row0 + rgrp * TM + i;
        if (r >= nrows) continue;
        int oc = cgrp * TN;
        if (oc >= OUTS) continue;
        float dv = dinv[r];
        float d2 = dv * dv;
        float v[TN], vi[TN];
        #pragma unroll
        for (int j = 0; j < TN; j++) {
            int o = oc + j;
            if (o < DOUT) {
                v[j]  = acc[i][j] + bs[o] + bb[o];
                vi[j] = v[j] * d2 + bg[o];
            } else { v[j] = 0.f; vi[j] = 0.f; }
        }
        *(float4*)(out_t + (size_t)r * OUTS + oc)     = *(float4*)&v[0];
        *(float4*)(out_t + (size_t)r * OUTS + oc + 4) = *(float4*)&v[4];
        *(float4*)(out_i + (size_t)r * OUTS + oc)     = *(float4*)&vi[0];
        *(float4*)(out_i + (size_t)r * OUTS + oc + 4) = *(float4*)&vi[4];
    }
}

// ---------------- edge aggregation: vectorized reductions ----------------
__device__ __forceinline__ void red_v4(float* p, float4 v) {
    asm volatile("red.global.add.v4.f32 [%0], {%1,%2,%3,%4};"
                 :: "l"(p), "f"(v.x), "f"(v.y), "f"(v.z), "f"(v.w) : "memory");
}

// F = 128: one warp per edge, one float4 per lane
__global__ void agg_edges128(const float* __restrict__ tin,
                             const int* __restrict__ src,
                             const int* __restrict__ dst,
                             const float* __restrict__ dinv,
                             float* __restrict__ out, int E) {
    int w = (blockIdx.x * blockDim.x + threadIdx.x) >> 5;
    int lane = threadIdx.x & 31;
    if (w >= E) return;
    int s = __ldg(src + w), d = __ldg(dst + w);
    float c = __ldg(dinv + s) * __ldg(dinv + d);
    float4 v = __ldg((const float4*)(tin + (size_t)s * 128) + lane);
    v.x *= c; v.y *= c; v.z *= c; v.w *= c;
    red_v4(out + (size_t)d * 128 + lane * 4, v);
}

// F = 48 (padded): 16 threads per edge, 12 active float4 lanes
__global__ void agg_edges48(const float* __restrict__ tin,
                            const int* __restrict__ src,
                            const int* __restrict__ dst,
                            const float* __restrict__ dinv,
                            float* __restrict__ out, int E) {
    int idx = blockIdx.x * blockDim.x + threadIdx.x;
    int e = idx >> 4, c = idx & 15;
    if (e >= E || c >= 12) return;
    int s = __ldg(src + e), d = __ldg(dst + e);
    float w = __ldg(dinv + s) * __ldg(dinv + d);
    float4 v = __ldg((const float4*)(tin + (size_t)s * 48) + c);
    v.x *= w; v.y *= w; v.z *= w; v.w *= w;
    red_v4(out + (size_t)d * 48 + c * 4, v);
}

// final: copy padded [N,48] -> [N,47]
__global__ void unpad_kernel(const float* __restrict__ pad, float* __restrict__ out, int n) {
    int idx = blockIdx.x * blockDim.x + threadIdx.x;
    if (idx >= n * 47) return;
    int r = idx / 47, f = idx - r * 47;
    out[idx] = pad[(size_t)r * 48 + f];
}

// ---------------- launch ----------------
extern "C" void kernel_launch(void* const* d_in, const int* in_sizes, int n_in,
                              void* d_out, int out_size) {
    const float* x  = (const float*)d_in[0];
    const int*   ei = (const int*)d_in[1];
    const int N = in_sizes[0] / FEAT;
    const int E = in_sizes[1] / 2;
    const int* e_src = ei;
    const int* e_dst = ei + E;

    const float* P[21];
    for (int i = 0; i < 21; i++) P[i] = (const float*)d_in[2 + i];

    float *deg, *t, *h1, *h2, *pad, *wt0, *wt1, *wt2;
    cudaGetSymbolAddress((void**)&deg, g_deg);
    cudaGetSymbolAddress((void**)&t,   g_t);
    cudaGetSymbolAddress((void**)&h1,  g_h1);
    cudaGetSymbolAddress((void**)&h2,  g_h2);
    cudaGetSymbolAddress((void**)&pad, g_pad);
    cudaGetSymbolAddress((void**)&wt0, g_wt0);
    cudaGetSymbolAddress((void**)&wt1, g_wt1);
    cudaGetSymbolAddress((void**)&wt2, g_wt2);
    float* out = (float*)d_out;

    // degree -> dinv
    deg_init_kernel<<<(N + 255) / 256, 256>>>(deg, N);
    deg_count_kernel<<<(E + 255) / 256, 256>>>(e_dst, deg, E);
    dinv_kernel<<<(N + 255) / 256, 256>>>(deg, N);

    // weight pre-transposes (tiny)
    wt_kernel<<<(640 * 128 + 255) / 256, 256>>>(P[2],  P[4],  wt0, 128, 128, 128);
    wt_kernel<<<(640 * 128 + 255) / 256, 256>>>(P[9],  P[11], wt1, 128, 128, 128);
    wt_kernel<<<(1920 * 48 + 255) / 256, 256>>>(P[16], P[18], wt2, 384, 47, 48);

    const int GB = (N + 127) / 128;

    // ---- layer 0
    fkan2<128, 128, 128, 8, 128><<<GB, 256>>>(
        x, nullptr, nullptr, P[0], P[1], wt0, P[3], P[5], P[6], deg, t, h1, N);
    agg_edges128<<<((size_t)E * 32 + 255) / 256, 256>>>(t, e_src, e_dst, deg, h1, E);

    // ---- layer 1
    fkan2<128, 128, 128, 8, 128><<<GB, 256>>>(
        h1, nullptr, nullptr, P[7], P[8], wt1, P[10], P[12], P[13], deg, t, h2, N);
    agg_edges128<<<((size_t)E * 32 + 255) / 256, 256>>>(t, e_src, e_dst, deg, h2, E);

    // ---- layer 2 (concat input, padded out width 48)
    fkan2<384, 47, 48, 4, 48><<<GB, 192>>>(
        x, h1, h2, P[14], P[15], wt2, P[17], P[19], P[20], deg, t, pad, N);
    agg_edges48<<<((size_t)E * 16 + 255) / 256, 256>>>(t, e_src, e_dst, deg, pad, E);
    unpad_kernel<<<(N * 47 + 255) / 256, 256>>>(pad, out, N);
}

// round 8
// speedup vs baseline: 2.1146x; 1.6496x over previous
#include <cuda_runtime.h>
#include <cuda_bf16.h>
#include <math.h>
#include <stdint.h>

#define NN 100000
#define FEAT 128

// ---------------- scratch (device globals; allocation-free) ----------------
__device__ __align__(16) float g_deg[NN];
__device__ __align__(16) float g_t[NN * 128];
__device__ __align__(16) float g_h1[NN * 128];
__device__ __align__(16) float g_h2[NN * 128];
__device__ __align__(16) float g_pad[NN * 48];
// pre-split, chunk-contiguous k-major weights: [chunk][n][64] bf16
__device__ __align__(16) __nv_bfloat16 g_w0hi[640 * 128], g_w0lo[640 * 128];
__device__ __align__(16) __nv_bfloat16 g_w1hi[640 * 128], g_w1lo[640 * 128];
__device__ __align__(16) __nv_bfloat16 g_w2hi[1920 * 64], g_w2lo[1920 * 64];

// ---------------- mma/ldmatrix helpers (baseline PTX, sm_80+) ----------------
__device__ __forceinline__ uint32_t smem_u32(const void* p) {
    uint32_t a;
    asm("{ .reg .u64 t; cvta.to.shared.u64 t, %1; cvt.u32.u64 %0, t; }" : "=r"(a) : "l"(p));
    return a;
}
__device__ __forceinline__ void ldmx4(uint32_t* r, uint32_t addr) {
    asm volatile("ldmatrix.sync.aligned.m8n8.x4.shared.b16 {%0,%1,%2,%3}, [%4];"
                 : "=r"(r[0]), "=r"(r[1]), "=r"(r[2]), "=r"(r[3]) : "r"(addr));
}
__device__ __forceinline__ void ldmx2(uint32_t* r, uint32_t addr) {
    asm volatile("ldmatrix.sync.aligned.m8n8.x2.shared.b16 {%0,%1}, [%2];"
                 : "=r"(r[0]), "=r"(r[1]) : "r"(addr));
}
__device__ __forceinline__ void mma16816(float* c, const uint32_t* a, const uint32_t* b) {
    asm volatile("mma.sync.aligned.m16n8k16.row.col.f32.bf16.bf16.f32 "
                 "{%0,%1,%2,%3}, {%4,%5,%6,%7}, {%8,%9}, {%0,%1,%2,%3};"
                 : "+f"(c[0]), "+f"(c[1]), "+f"(c[2]), "+f"(c[3])
                 : "r"(a[0]), "r"(a[1]), "r"(a[2]), "r"(a[3]), "r"(b[0]), "r"(b[1]));
}

// ---------------- degree ----------------
__global__ void deg_init_kernel(float* deg, int n) {
    int i = blockIdx.x * blockDim.x + threadIdx.x;
    if (i < n) deg[i] = 1.0f;
}
__global__ void deg_count_kernel(const int* __restrict__ dst, float* deg, int E) {
    int e = blockIdx.x * blockDim.x + threadIdx.x;
    if (e < E) atomicAdd(&deg[dst[e]], 1.0f);
}
__global__ void dinv_kernel(float* deg, int n) {
    int i = blockIdx.x * blockDim.x + threadIdx.x;
    if (i < n) deg[i] = rsqrtf(deg[i]);
}

// ---------------- weight split/transpose ----------------
// k = d*4+g for rbf (k < 4*DIN), k = 4*DIN + d for silu.
// out: chunk-contiguous [c][n][64] bf16, zero-pad n >= DOUT.
__global__ void wt_split(const float* __restrict__ Ws, const float* __restrict__ Wb,
                         __nv_bfloat16* __restrict__ Whi, __nv_bfloat16* __restrict__ Wlo,
                         int DIN, int DOUT, int BN) {
    int idx = blockIdx.x * blockDim.x + threadIdx.x;
    int tot = DIN * 5 * BN;
    if (idx >= tot) return;
    int kl = idx & 63;
    int rest = idx >> 6;
    int n = rest % BN;
    int c = rest / BN;
    int k = c * 64 + kl;
    float v = 0.f;
    if (n < DOUT) {
        if (k < 4 * DIN) { int d = k >> 2, g = k & 3; v = Ws[(size_t)n * (DIN * 4) + d * 4 + g]; }
        else             { v = Wb[(size_t)n * DIN + (k - 4 * DIN)]; }
    }
    __nv_bfloat16 hi = __float2bfloat16_rn(v);
    float lo = v - __bfloat162float(hi);
    size_t o = (size_t)c * BN * 64 + (size_t)n * 64 + kl;
    Whi[o] = hi;
    Wlo[o] = __float2bfloat16_rn(lo);
}

// ---------------- input loader (layer 2 = concat [x|h1|h2]) ----------------
template <int DIN>
__device__ __forceinline__ float4 loadX4(const float* __restrict__ X0,
                                         const float* __restrict__ X1,
                                         const float* __restrict__ X2,
                                         int r, int d) {
    if constexpr (DIN == 384) {
        if (d < 128)      return *(const float4*)(X0 + (size_t)r * 128 + d);
        else if (d < 256) return *(const float4*)(X1 + (size_t)r * 128 + (d - 128));
        else              return *(const float4*)(X2 + (size_t)r * 128 + (d - 256));
    } else {
        return *(const float4*)(X0 + (size_t)r * DIN + d);
    }
}

// pack 4 floats -> bf16 hi uint2 + bf16 lo uint2
__device__ __forceinline__ void pack4(char* hibase, char* lobase, uint32_t off,
                                      float v0, float v1, float v2, float v3) {
    __nv_bfloat16 h0 = __float2bfloat16_rn(v0), h1 = __float2bfloat16_rn(v1);
    __nv_bfloat16 h2 = __float2bfloat16_rn(v2), h3 = __float2bfloat16_rn(v3);
    uint2 u;
    u.x = (uint32_t)__bfloat16_as_ushort(h0) | ((uint32_t)__bfloat16_as_ushort(h1) << 16);
    u.y = (uint32_t)__bfloat16_as_ushort(h2) | ((uint32_t)__bfloat16_as_ushort(h3) << 16);
    *(uint2*)(hibase + off) = u;
    __nv_bfloat16 l0 = __float2bfloat16_rn(v0 - __bfloat162float(h0));
    __nv_bfloat16 l1 = __float2bfloat16_rn(v1 - __bfloat162float(h1));
    __nv_bfloat16 l2 = __float2bfloat16_rn(v2 - __bfloat162float(h2));
    __nv_bfloat16 l3 = __float2bfloat16_rn(v3 - __bfloat162float(h3));
    uint2 w;
    w.x = (uint32_t)__bfloat16_as_ushort(l0) | ((uint32_t)__bfloat16_as_ushort(l1) << 16);
    w.y = (uint32_t)__bfloat16_as_ushort(l2) | ((uint32_t)__bfloat16_as_ushort(l3) << 16);
    *(uint2*)(lobase + off) = w;
}

// ---------------- fused FastKAN layer (mma.sync bf16 hi/lo) ----------------
// smem rows padded to PK=72 bf16 (144 B): ldmatrix rows step 36 banks -> 4-bank
// stride per row -> conflict-free 8-row tiles.
template <int DIN, int DOUT, int BN, int OUTS>
__global__ void __launch_bounds__(256)
fkan4(const float* __restrict__ X0, const float* __restrict__ X1,
      const float* __restrict__ X2,
      const float* __restrict__ gam, const float* __restrict__ bet,
      const __nv_bfloat16* __restrict__ WhiG, const __nv_bfloat16* __restrict__ WloG,
      const float* __restrict__ bs, const float* __restrict__ bb,
      const float* __restrict__ bg, const float* __restrict__ dinv,
      float* __restrict__ out_t, float* __restrict__ out_i, int nrows) {
    constexpr int BM = 128;
    constexpr int PK = 72;                  // padded row length (bf16)
    constexpr int AROWB = PK * 2;           // 144 bytes
    constexpr int CRBF = DIN / 16;          // rbf chunks (16 d * 4 g = 64 k)
    constexpr int CTOT = DIN * 5 / 64;      // total 64-k chunks
    constexpr int NT_ = BN / 16;            // n8 tiles per warp (warp covers BN/2 cols)

    extern __shared__ char sm[];
    char* AHc = sm;
    char* ALc = sm + BM * AROWB;
    char* WHc = sm + 2 * BM * AROWB;
    char* WLc = WHc + BN * AROWB;
    __shared__ float sMu[BM], sRs[BM];

    const int t = threadIdx.x;
    const int wid = t >> 5;
    const int lane = t & 31;
    const int row0 = blockIdx.x * BM;
    const uint32_t sbase = smem_u32(sm);
    const uint32_t aAH = sbase;
    const uint32_t aWH = sbase + 2 * BM * AROWB;

    // ---- layernorm stats: one warp per node ----
    for (int n = wid; n < BM; n += 8) {
        int r = row0 + n;
        float s = 0.f, ss = 0.f;
        if (r < nrows) {
            for (int d4 = lane; d4 < DIN / 4; d4 += 32) {
                float4 v = loadX4<DIN>(X0, X1, X2, r, d4 * 4);
                s  += v.x + v.y + v.z + v.w;
                ss += v.x * v.x + v.y * v.y + v.z * v.z + v.w * v.w;
            }
        }
        #pragma unroll
        for (int off = 16; off; off >>= 1) {
            s  += __shfl_xor_sync(0xffffffffu, s,  off);
            ss += __shfl_xor_sync(0xffffffffu, ss, off);
        }
        if (lane == 0) {
            if (r < nrows) {
                float mu = s * (1.0f / DIN);
                float var = ss * (1.0f / DIN) - mu * mu;
                sMu[n] = mu; sRs[n] = rsqrtf(var + 1e-5f);
            } else { sMu[n] = 0.f; sRs[n] = 0.f; }
        }
    }
    __syncthreads();

    float acc[2][NT_][4];
    #pragma unroll
    for (int mt = 0; mt < 2; mt++)
        #pragma unroll
        for (int nt = 0; nt < NT_; nt++)
            #pragma unroll
            for (int j = 0; j < 4; j++) acc[mt][nt][j] = 0.f;

    const int wr = (wid >> 1) * 32;          // warp row base
    const int wc = (wid & 1) * (BN / 2);     // warp col base
    const int am = wr + (lane & 15);
    const int akh = lane >> 4;
    const int bnr = lane & 7;
    const int bkh = (lane >> 3) & 1;

    const float GR[4] = {-2.0f, -2.0f / 3.0f, 2.0f / 3.0f, 2.0f};

    for (int c = 0; c < CTOT; ++c) {
        // ---- build A chunk (hi/lo bf16) ----
        if (c < CRBF) {
            for (int p = t; p < BM * 4; p += 256) {
                int n = p >> 2, q = p & 3;
                int d = c * 16 + q * 4;
                int r = row0 + n;
                float4 xv = make_float4(0.f, 0.f, 0.f, 0.f);
                if (r < nrows) xv = loadX4<DIN>(X0, X1, X2, r, d);
                float4 gv = *(const float4*)(gam + d);
                float4 bv = *(const float4*)(bet + d);
                float mu = sMu[n], rs = sRs[n];
                float xs[4] = {xv.x, xv.y, xv.z, xv.w};
                float gs[4] = {gv.x, gv.y, gv.z, gv.w};
                float bs4[4] = {bv.x, bv.y, bv.z, bv.w};
                #pragma unroll
                for (int j = 0; j < 4; j++) {
                    float z = (xs[j] - mu) * rs * gs[j] + bs4[j];
                    float u0 = (z - GR[0]) * 0.75f;
                    float u1 = (z - GR[1]) * 0.75f;
                    float u2 = (z - GR[2]) * 0.75f;
                    float u3 = (z - GR[3]) * 0.75f;
                    uint32_t off = (uint32_t)n * AROWB + (uint32_t)(q * 4 + j) * 8;
                    pack4(AHc, ALc, off, __expf(-u0 * u0), __expf(-u1 * u1),
                          __expf(-u2 * u2), __expf(-u3 * u3));
                }
            }
        } else {
            int ds0 = (c - CRBF) * 64;
            for (int p = t; p < BM * 16; p += 256) {
                int n = p >> 4, q = p & 15;
                int d = ds0 + q * 4;
                int r = row0 + n;
                float4 xv = make_float4(0.f, 0.f, 0.f, 0.f);
                if (r < nrows) xv = loadX4<DIN>(X0, X1, X2, r, d);
                float s0 = xv.x / (1.0f + __expf(-xv.x));
                float s1 = xv.y / (1.0f + __expf(-xv.y));
                float s2 = xv.z / (1.0f + __expf(-xv.z));
                float s3 = xv.w / (1.0f + __expf(-xv.w));
                uint32_t off = (uint32_t)n * AROWB + (uint32_t)q * 8;
                pack4(AHc, ALc, off, s0, s1, s2, s3);
            }
        }
        // ---- copy W chunk into padded smem rows ----
        {
            const uint4* sh = (const uint4*)(WhiG + (size_t)c * BN * 64);
            const uint4* sl = (const uint4*)(WloG + (size_t)c * BN * 64);
            for (int p = t; p < BN * 8; p += 256) {
                int n = p >> 3, i = p & 7;
                *(uint4*)(WHc + n * AROWB + i * 16) = sh[n * 8 + i];
                *(uint4*)(WLc + n * AROWB + i * 16) = sl[n * 8 + i];
            }
        }
        __syncthreads();

        // ---- tensor-core GEMM on the chunk ----
        #pragma unroll
        for (int ks = 0; ks < 4; ks++) {
            uint32_t ahi[2][4], alo[2][4], bhi[NT_][2], blo[NT_][2];
            #pragma unroll
            for (int mt = 0; mt < 2; mt++) {
                uint32_t ad = aAH + (uint32_t)(am + mt * 16) * AROWB + ks * 32 + akh * 16;
                ldmx4(ahi[mt], ad);
                ldmx4(alo[mt], ad + (uint32_t)BM * AROWB);
            }
            #pragma unroll
            for (int nt = 0; nt < NT_; nt++) {
                uint32_t bd = aWH + (uint32_t)(wc + nt * 8 + bnr) * AROWB + ks * 32 + bkh * 16;
                ldmx2(bhi[nt], bd);
                ldmx2(blo[nt], bd + (uint32_t)BN * AROWB);
            }
            #pragma unroll
            for (int mt = 0; mt < 2; mt++)
                #pragma unroll
                for (int nt = 0; nt < NT_; nt++) {
                    mma16816(acc[mt][nt], ahi[mt], bhi[nt]);
                    mma16816(acc[mt][nt], ahi[mt], blo[nt]);
                    mma16816(acc[mt][nt], alo[mt], bhi[nt]);
                }
        }
        __syncthreads();
    }

    // ---- epilogue: biases + fused self-loop init, straight from registers ----
    const int rb = row0 + wr + (lane >> 2);
    const int cb = wc + (lane & 3) * 2;
    #pragma unroll
    for (int mt = 0; mt < 2; mt++) {
        #pragma unroll
        for (int h = 0; h < 2; h++) {
            int r = rb + mt * 16 + h * 8;
            if (r >= nrows) continue;
            float dv = __ldg(dinv + r);
            float d2 = dv * dv;
            #pragma unroll
            for (int nt = 0; nt < NT_; nt++) {
                int o = cb + nt * 8;
                if (o >= OUTS) continue;
                float a0 = acc[mt][nt][h * 2 + 0];
                float a1 = acc[mt][nt][h * 2 + 1];
                float v0 = (o < DOUT)     ? a0 + __ldg(bs + o)     + __ldg(bb + o)     : 0.f;
                float v1 = (o + 1 < DOUT) ? a1 + __ldg(bs + o + 1) + __ldg(bb + o + 1) : 0.f;
                float i0 = (o < DOUT)     ? v0 * d2 + __ldg(bg + o)     : 0.f;
                float i1 = (o + 1 < DOUT) ? v1 * d2 + __ldg(bg + o + 1) : 0.f;
                *(float2*)(out_t + (size_t)r * OUTS + o) = make_float2(v0, v1);
                *(float2*)(out_i + (size_t)r * OUTS + o) = make_float2(i0, i1);
            }
        }
    }
}

// ---------------- edge aggregation ----------------
__device__ __forceinline__ void red_v4(float* p, float4 v) {
    asm volatile("red.global.add.v4.f32 [%0], {%1,%2,%3,%4};"
                 :: "l"(p), "f"(v.x), "f"(v.y), "f"(v.z), "f"(v.w) : "memory");
}
__global__ void agg_edges128(const float* __restrict__ tin,
                             const int* __restrict__ src,
                             const int* __restrict__ dst,
                             const float* __restrict__ dinv,
                             float* __restrict__ out, int E) {
    int w = (blockIdx.x * blockDim.x + threadIdx.x) >> 5;
    int lane = threadIdx.x & 31;
    if (w >= E) return;
    int s = __ldg(src + w), d = __ldg(dst + w);
    float c = __ldg(dinv + s) * __ldg(dinv + d);
    float4 v = __ldg((const float4*)(tin + (size_t)s * 128) + lane);
    v.x *= c; v.y *= c; v.z *= c; v.w *= c;
    red_v4(out + (size_t)d * 128 + lane * 4, v);
}
__global__ void agg_edges48(const float* __restrict__ tin,
                            const int* __restrict__ src,
                            const int* __restrict__ dst,
                            const float* __restrict__ dinv,
                            float* __restrict__ out, int E) {
    int idx = blockIdx.x * blockDim.x + threadIdx.x;
    int e = idx >> 4, c = idx & 15;
    if (e >= E || c >= 12) return;
    int s = __ldg(src + e), d = __ldg(dst + e);
    float w = __ldg(dinv + s) * __ldg(dinv + d);
    float4 v = __ldg((const float4*)(tin + (size_t)s * 48) + c);
    v.x *= w; v.y *= w; v.z *= w; v.w *= w;
    red_v4(out + (size_t)d * 48 + c * 4, v);
}
__global__ void unpad_kernel(const float* __restrict__ pad, float* __restrict__ out, int n) {
    int idx = blockIdx.x * blockDim.x + threadIdx.x;
    if (idx >= n * 47) return;
    int r = idx / 47, f = idx - r * 47;
    out[idx] = pad[(size_t)r * 48 + f];
}

// ---------------- launch ----------------
extern "C" void kernel_launch(void* const* d_in, const int* in_sizes, int n_in,
                              void* d_out, int out_size) {
    const float* x  = (const float*)d_in[0];
    const int*   ei = (const int*)d_in[1];
    const int N = in_sizes[0] / FEAT;
    const int E = in_sizes[1] / 2;
    const int* e_src = ei;
    const int* e_dst = ei + E;

    const float* P[21];
    for (int i = 0; i < 21; i++) P[i] = (const float*)d_in[2 + i];

    float *deg, *t, *h1, *h2, *pad;
    __nv_bfloat16 *w0hi, *w0lo, *w1hi, *w1lo, *w2hi, *w2lo;
    cudaGetSymbolAddress((void**)&deg, g_deg);
    cudaGetSymbolAddress((void**)&t,   g_t);
    cudaGetSymbolAddress((void**)&h1,  g_h1);
    cudaGetSymbolAddress((void**)&h2,  g_h2);
    cudaGetSymbolAddress((void**)&pad, g_pad);
    cudaGetSymbolAddress((void**)&w0hi, g_w0hi);
    cudaGetSymbolAddress((void**)&w0lo, g_w0lo);
    cudaGetSymbolAddress((void**)&w1hi, g_w1hi);
    cudaGetSymbolAddress((void**)&w1lo, g_w1lo);
    cudaGetSymbolAddress((void**)&w2hi, g_w2hi);
    cudaGetSymbolAddress((void**)&w2lo, g_w2lo);
    float* out = (float*)d_out;

    deg_init_kernel<<<(N + 255) / 256, 256>>>(deg, N);
    deg_count_kernel<<<(E + 255) / 256, 256>>>(e_dst, deg, E);
    dinv_kernel<<<(N + 255) / 256, 256>>>(deg, N);

    wt_split<<<(640 * 128 + 255) / 256, 256>>>(P[2],  P[4],  w0hi, w0lo, 128, 128, 128);
    wt_split<<<(640 * 128 + 255) / 256, 256>>>(P[9],  P[11], w1hi, w1lo, 128, 128, 128);
    wt_split<<<(1920 * 64 + 255) / 256, 256>>>(P[16], P[18], w2hi, w2lo, 384, 47, 64);

    const int SM01 = (2 * 128 + 2 * 128) * 144;  // 73728 B
    const int SM2  = (2 * 128 + 2 * 64)  * 144;  // 55296 B
    cudaFuncSetAttribute(fkan4<128, 128, 128, 128>,
                         cudaFuncAttributeMaxDynamicSharedMemorySize, SM01);
    cudaFuncSetAttribute(fkan4<384, 47, 64, 48>,
                         cudaFuncAttributeMaxDynamicSharedMemorySize, SM2);

    const int GB = (N + 127) / 128;

    // ---- layer 0
    fkan4<128, 128, 128, 128><<<GB, 256, SM01>>>(
        x, nullptr, nullptr, P[0], P[1], w0hi, w0lo, P[3], P[5], P[6], deg, t, h1, N);
    agg_edges128<<<((size_t)E * 32 + 255) / 256, 256>>>(t, e_src, e_dst, deg, h1, E);

    // ---- layer 1
    fkan4<128, 128, 128, 128><<<GB, 256, SM01>>>(
        h1, nullptr, nullptr, P[7], P[8], w1hi, w1lo, P[10], P[12], P[13], deg, t, h2, N);
    agg_edges128<<<((size_t)E * 32 + 255) / 256, 256>>>(t, e_src, e_dst, deg, h2, E);

    // ---- layer 2 (concat input, padded out width 48)
    fkan4<384, 47, 64, 48><<<GB, 256, SM2>>>(
        x, h1, h2, P[14], P[15], w2hi, w2lo, P[17], P[19], P[20], deg, t, pad, N);
    agg_edges48<<<((size_t)E * 16 + 255) / 256, 256>>>(t, e_src, e_dst, deg, pad, E);
    unpad_kernel<<<(N * 47 + 255) / 256, 256>>>(pad, out, N);
}

// round 10
// speedup vs baseline: 2.6906x; 1.2724x over previous
#include <cuda_runtime.h>
#include <cuda_bf16.h>
#include <math.h>
#include <stdint.h>

#define NN 100000
#define EE 1600000
#define FEAT 128

// ---------------- scratch (device globals; allocation-free) ----------------
__device__ __align__(16) float g_t[NN * 128];
__device__ __align__(16) float g_h1[NN * 128];
__device__ __align__(16) float g_h2[NN * 128];
// CSR build
__device__ __align__(16) int   g_counts[NN];
__device__ __align__(16) int   g_psum[NN];
__device__ __align__(16) int   g_bsum[128];
__device__ __align__(16) int   g_boff[128];
__device__ __align__(16) int   g_rowptr[NN + 1];
__device__ __align__(16) int   g_cursor[NN];
__device__ __align__(16) int   g_col[EE];
__device__ __align__(16) float g_wv[EE];
__device__ __align__(16) float g_dinv[NN];
// pre-split, chunk-contiguous k-major weights: [chunk][n][64] bf16
__device__ __align__(16) __nv_bfloat16 g_w0hi[640 * 128], g_w0lo[640 * 128];
__device__ __align__(16) __nv_bfloat16 g_w1hi[640 * 128], g_w1lo[640 * 128];
__device__ __align__(16) __nv_bfloat16 g_w2hi[1920 * 64], g_w2lo[1920 * 64];

// ---------------- mma/ldmatrix helpers (baseline PTX, sm_80+) ----------------
__device__ __forceinline__ uint32_t smem_u32(const void* p) {
    uint32_t a;
    asm("{ .reg .u64 t; cvta.to.shared.u64 t, %1; cvt.u32.u64 %0, t; }" : "=r"(a) : "l"(p));
    return a;
}
__device__ __forceinline__ void ldmx4(uint32_t* r, uint32_t addr) {
    asm volatile("ldmatrix.sync.aligned.m8n8.x4.shared.b16 {%0,%1,%2,%3}, [%4];"
                 : "=r"(r[0]), "=r"(r[1]), "=r"(r[2]), "=r"(r[3]) : "r"(addr));
}
__device__ __forceinline__ void ldmx2(uint32_t* r, uint32_t addr) {
    asm volatile("ldmatrix.sync.aligned.m8n8.x2.shared.b16 {%0,%1}, [%2];"
                 : "=r"(r[0]), "=r"(r[1]) : "r"(addr));
}
__device__ __forceinline__ void mma16816(float* c, const uint32_t* a, const uint32_t* b) {
    asm volatile("mma.sync.aligned.m16n8k16.row.col.f32.bf16.bf16.f32 "
                 "{%0,%1,%2,%3}, {%4,%5,%6,%7}, {%8,%9}, {%0,%1,%2,%3};"
                 : "+f"(c[0]), "+f"(c[1]), "+f"(c[2]), "+f"(c[3])
                 : "r"(a[0]), "r"(a[1]), "r"(a[2]), "r"(a[3]), "r"(b[0]), "r"(b[1]));
}

// ---------------- CSR build ----------------
__global__ void zero_counts(int* c, int n) {
    int i = blockIdx.x * blockDim.x + threadIdx.x;
    if (i < n) c[i] = 0;
}
__global__ void hist_kernel(const int* __restrict__ dst, int* c, int E) {
    int e = blockIdx.x * blockDim.x + threadIdx.x;
    if (e < E) atomicAdd(&c[dst[e]], 1);
}
__global__ void scan_partial(const int* __restrict__ counts, int* psum, int* bsum, int n) {
    __shared__ int s[1024];
    int t = threadIdx.x, b = blockIdx.x;
    int i = b * 1024 + t;
    int v = (i < n) ? counts[i] : 0;
    s[t] = v;
    __syncthreads();
    for (int off = 1; off < 1024; off <<= 1) {
        int x = (t >= off) ? s[t - off] : 0;
        __syncthreads();
        s[t] += x;
        __syncthreads();
    }
    if (i < n) psum[i] = s[t] - v;           // exclusive
    if (t == 1023) bsum[b] = s[1023];
}
__global__ void scan_tops(const int* __restrict__ bsum, int* boff, int nb) {
    __shared__ int s[128];
    int t = threadIdx.x;
    int v = (t < nb) ? bsum[t] : 0;
    s[t] = v;
    __syncthreads();
    for (int off = 1; off < 128; off <<= 1) {
        int x = (t >= off) ? s[t - off] : 0;
        __syncthreads();
        s[t] += x;
        __syncthreads();
    }
    if (t < nb) boff[t] = s[t] - v;          // exclusive
}
__global__ void scan_final(const int* __restrict__ psum, const int* __restrict__ boff,
                           const int* __restrict__ counts,
                           int* rowptr, int* cursor, float* dinv, int n, int E) {
    int i = blockIdx.x * blockDim.x + threadIdx.x;
    if (i < n) {
        int v = psum[i] + boff[i >> 10];
        rowptr[i] = v;
        cursor[i] = v;
        dinv[i] = rsqrtf((float)(counts[i] + 1));   // +1 self loop
    } else if (i == n) {
        rowptr[n] = E;
    }
}
__global__ void scatter_kernel(const int* __restrict__ src, const int* __restrict__ dst,
                               const float* __restrict__ dinv,
                               int* cursor, int* col, float* wv, int E) {
    int e = blockIdx.x * blockDim.x + threadIdx.x;
    if (e >= E) return;
    int d = dst[e], s = src[e];
    int p = atomicAdd(&cursor[d], 1);
    col[p] = s;
    wv[p] = __ldg(dinv + s) * __ldg(dinv + d);
}

// ---------------- weight split/transpose ----------------
__global__ void wt_split(const float* __restrict__ Ws, const float* __restrict__ Wb,
                         __nv_bfloat16* __restrict__ Whi, __nv_bfloat16* __restrict__ Wlo,
                         int DIN, int DOUT, int BN) {
    int idx = blockIdx.x * blockDim.x + threadIdx.x;
    int tot = DIN * 5 * BN;
    if (idx >= tot) return;
    int kl = idx & 63;
    int rest = idx >> 6;
    int n = rest % BN;
    int c = rest / BN;
    int k = c * 64 + kl;
    float v = 0.f;
    if (n < DOUT) {
        if (k < 4 * DIN) { int d = k >> 2, g = k & 3; v = Ws[(size_t)n * (DIN * 4) + d * 4 + g]; }
        else             { v = Wb[(size_t)n * DIN + (k - 4 * DIN)]; }
    }
    __nv_bfloat16 hi = __float2bfloat16_rn(v);
    float lo = v - __bfloat162float(hi);
    size_t o = (size_t)c * BN * 64 + (size_t)n * 64 + kl;
    Whi[o] = hi;
    Wlo[o] = __float2bfloat16_rn(lo);
}

// ---------------- input loader (layer 2 = concat [x|h1|h2]) ----------------
template <int DIN>
__device__ __forceinline__ float4 loadX4(const float* __restrict__ X0,
                                         const float* __restrict__ X1,
                                         const float* __restrict__ X2,
                                         int r, int d) {
    if constexpr (DIN == 384) {
        if (d < 128)      return *(const float4*)(X0 + (size_t)r * 128 + d);
        else if (d < 256) return *(const float4*)(X1 + (size_t)r * 128 + (d - 128));
        else              return *(const float4*)(X2 + (size_t)r * 128 + (d - 256));
    } else {
        return *(const float4*)(X0 + (size_t)r * DIN + d);
    }
}

__device__ __forceinline__ void pack4(char* hibase, char* lobase, uint32_t off,
                                      float v0, float v1, float v2, float v3) {
    __nv_bfloat16 h0 = __float2bfloat16_rn(v0), h1 = __float2bfloat16_rn(v1);
    __nv_bfloat16 h2 = __float2bfloat16_rn(v2), h3 = __float2bfloat16_rn(v3);
    uint2 u;
    u.x = (uint32_t)__bfloat16_as_ushort(h0) | ((uint32_t)__bfloat16_as_ushort(h1) << 16);
    u.y = (uint32_t)__bfloat16_as_ushort(h2) | ((uint32_t)__bfloat16_as_ushort(h3) << 16);
    *(uint2*)(hibase + off) = u;
    __nv_bfloat16 l0 = __float2bfloat16_rn(v0 - __bfloat162float(h0));
    __nv_bfloat16 l1 = __float2bfloat16_rn(v1 - __bfloat162float(h1));
    __nv_bfloat16 l2 = __float2bfloat16_rn(v2 - __bfloat162float(h2));
    __nv_bfloat16 l3 = __float2bfloat16_rn(v3 - __bfloat162float(h3));
    uint2 w;
    w.x = (uint32_t)__bfloat16_as_ushort(l0) | ((uint32_t)__bfloat16_as_ushort(l1) << 16);
    w.y = (uint32_t)__bfloat16_as_ushort(l2) | ((uint32_t)__bfloat16_as_ushort(l3) << 16);
    *(uint2*)(lobase + off) = w;
}

// ---------------- fused FastKAN layer (mma.sync bf16 hi/lo) ----------------
template <int DIN, int DOUT, int BN, int OUTS>
__global__ void __launch_bounds__(256)
fkan4(const float* __restrict__ X0, const float* __restrict__ X1,
      const float* __restrict__ X2,
      const float* __restrict__ gam, const float* __restrict__ bet,
      const __nv_bfloat16* __restrict__ WhiG, const __nv_bfloat16* __restrict__ WloG,
      const float* __restrict__ bs, const float* __restrict__ bb,
      float* __restrict__ out_t, int nrows) {
    constexpr int BM = 128;
    constexpr int PK = 72;
    constexpr int AROWB = PK * 2;           // 144 bytes
    constexpr int CRBF = DIN / 16;
    constexpr int CTOT = DIN * 5 / 64;
    constexpr int NT_ = BN / 16;

    extern __shared__ char sm[];
    char* AHc = sm;
    char* ALc = sm + BM * AROWB;
    char* WHc = sm + 2 * BM * AROWB;
    char* WLc = WHc + BN * AROWB;
    __shared__ float sMu[BM], sRs[BM];

    const int t = threadIdx.x;
    const int wid = t >> 5;
    const int lane = t & 31;
    const int row0 = blockIdx.x * BM;
    const uint32_t sbase = smem_u32(sm);
    const uint32_t aAH = sbase;
    const uint32_t aWH = sbase + 2 * BM * AROWB;

    for (int n = wid; n < BM; n += 8) {
        int r = row0 + n;
        float s = 0.f, ss = 0.f;
        if (r < nrows) {
            for (int d4 = lane; d4 < DIN / 4; d4 += 32) {
                float4 v = loadX4<DIN>(X0, X1, X2, r, d4 * 4);
                s  += v.x + v.y + v.z + v.w;
                ss += v.x * v.x + v.y * v.y + v.z * v.z + v.w * v.w;
            }
        }
        #pragma unroll
        for (int off = 16; off; off >>= 1) {
            s  += __shfl_xor_sync(0xffffffffu, s,  off);
            ss += __shfl_xor_sync(0xffffffffu, ss, off);
        }
        if (lane == 0) {
            if (r < nrows) {
                float mu = s * (1.0f / DIN);
                float var = ss * (1.0f / DIN) - mu * mu;
                sMu[n] = mu; sRs[n] = rsqrtf(var + 1e-5f);
            } else { sMu[n] = 0.f; sRs[n] = 0.f; }
        }
    }
    __syncthreads();

    float acc[2][NT_][4];
    #pragma unroll
    for (int mt = 0; mt < 2; mt++)
        #pragma unroll
        for (int nt = 0; nt < NT_; nt++)
            #pragma unroll
            for (int j = 0; j < 4; j++) acc[mt][nt][j] = 0.f;

    const int wr = (wid >> 1) * 32;
    const int wc = (wid & 1) * (BN / 2);
    const int am = wr + (lane & 15);
    const int akh = lane >> 4;
    const int bnr = lane & 7;
    const int bkh = (lane >> 3) & 1;

    const float GR[4] = {-2.0f, -2.0f / 3.0f, 2.0f / 3.0f, 2.0f};

    for (int c = 0; c < CTOT; ++c) {
        if (c < CRBF) {
            for (int p = t; p < BM * 4; p += 256) {
                int n = p >> 2, q = p & 3;
                int d = c * 16 + q * 4;
                int r = row0 + n;
                float4 xv = make_float4(0.f, 0.f, 0.f, 0.f);
                if (r < nrows) xv = loadX4<DIN>(X0, X1, X2, r, d);
                float4 gv = *(const float4*)(gam + d);
                float4 bv = *(const float4*)(bet + d);
                float mu = sMu[n], rs = sRs[n];
                float xs[4] = {xv.x, xv.y, xv.z, xv.w};
                float gs[4] = {gv.x, gv.y, gv.z, gv.w};
                float bs4[4] = {bv.x, bv.y, bv.z, bv.w};
                #pragma unroll
                for (int j = 0; j < 4; j++) {
                    float z = (xs[j] - mu) * rs * gs[j] + bs4[j];
                    float u0 = (z - GR[0]) * 0.75f;
                    float u1 = (z - GR[1]) * 0.75f;
                    float u2 = (z - GR[2]) * 0.75f;
                    float u3 = (z - GR[3]) * 0.75f;
                    uint32_t off = (uint32_t)n * AROWB + (uint32_t)(q * 4 + j) * 8;
                    pack4(AHc, ALc, off, __expf(-u0 * u0), __expf(-u1 * u1),
                          __expf(-u2 * u2), __expf(-u3 * u3));
                }
            }
        } else {
            int ds0 = (c - CRBF) * 64;
            for (int p = t; p < BM * 16; p += 256) {
                int n = p >> 4, q = p & 15;
                int d = ds0 + q * 4;
                int r = row0 + n;
                float4 xv = make_float4(0.f, 0.f, 0.f, 0.f);
                if (r < nrows) xv = loadX4<DIN>(X0, X1, X2, r, d);
                float s0 = xv.x / (1.0f + __expf(-xv.x));
                float s1 = xv.y / (1.0f + __expf(-xv.y));
                float s2 = xv.z / (1.0f + __expf(-xv.z));
                float s3 = xv.w / (1.0f + __expf(-xv.w));
                uint32_t off = (uint32_t)n * AROWB + (uint32_t)q * 8;
                pack4(AHc, ALc, off, s0, s1, s2, s3);
            }
        }
        {
            const uint4* sh = (const uint4*)(WhiG + (size_t)c * BN * 64);
            const uint4* sl = (const uint4*)(WloG + (size_t)c * BN * 64);
            for (int p = t; p < BN * 8; p += 256) {
                int n = p >> 3, i = p & 7;
                *(uint4*)(WHc + n * AROWB + i * 16) = sh[n * 8 + i];
                *(uint4*)(WLc + n * AROWB + i * 16) = sl[n * 8 + i];
            }
        }
        __syncthreads();

        #pragma unroll
        for (int ks = 0; ks < 4; ks++) {
            uint32_t ahi[2][4], alo[2][4], bhi[NT_][2], blo[NT_][2];
            #pragma unroll
            for (int mt = 0; mt < 2; mt++) {
                uint32_t ad = aAH + (uint32_t)(am + mt * 16) * AROWB + ks * 32 + akh * 16;
                ldmx4(ahi[mt], ad);
                ldmx4(alo[mt], ad + (uint32_t)BM * AROWB);
            }
            #pragma unroll
            for (int nt = 0; nt < NT_; nt++) {
                uint32_t bd = aWH + (uint32_t)(wc + nt * 8 + bnr) * AROWB + ks * 32 + bkh * 16;
                ldmx2(bhi[nt], bd);
                ldmx2(blo[nt], bd + (uint32_t)BN * AROWB);
            }
            #pragma unroll
            for (int mt = 0; mt < 2; mt++)
                #pragma unroll
                for (int nt = 0; nt < NT_; nt++) {
                    mma16816(acc[mt][nt], ahi[mt], bhi[nt]);
                    mma16816(acc[mt][nt], ahi[mt], blo[nt]);
                    mma16816(acc[mt][nt], alo[mt], bhi[nt]);
                }
        }
        __syncthreads();
    }

    // ---- epilogue: biases only (self-loop/bias handled by gather) ----
    const int rb = row0 + wr + (lane >> 2);
    const int cb = wc + (lane & 3) * 2;
    #pragma unroll
    for (int mt = 0; mt < 2; mt++) {
        #pragma unroll
        for (int h = 0; h < 2; h++) {
            int r = rb + mt * 16 + h * 8;
            if (r >= nrows) continue;
            #pragma unroll
            for (int nt = 0; nt < NT_; nt++) {
                int o = cb + nt * 8;
                if (o >= OUTS) continue;
                float a0 = acc[mt][nt][h * 2 + 0];
                float a1 = acc[mt][nt][h * 2 + 1];
                float v0 = (o < DOUT)     ? a0 + __ldg(bs + o)     + __ldg(bb + o)     : 0.f;
                float v1 = (o + 1 < DOUT) ? a1 + __ldg(bs + o + 1) + __ldg(bb + o + 1) : 0.f;
                *(float2*)(out_t + (size_t)r * OUTS + o) = make_float2(v0, v1);
            }
        }
    }
}

// ---------------- CSR gather aggregation ----------------
// out[r] = bg + dinv[r]^2 * t[r] + sum_e w[e] * t[col[e]]
__global__ void __launch_bounds__(256)
gat128(const float* __restrict__ tin, const int* __restrict__ rowptr,
       const int* __restrict__ col, const float* __restrict__ wv,
       const float* __restrict__ dinv, const float* __restrict__ bg,
       float* __restrict__ out, int n) {
    int wrp = (blockIdx.x * blockDim.x + threadIdx.x) >> 5;
    int lane = threadIdx.x & 31;
    if (wrp >= n) return;
    int beg = __ldg(rowptr + wrp), end = __ldg(rowptr + wrp + 1);
    float dv = __ldg(dinv + wrp);
    float d2 = dv * dv;
    float4 acc = __ldg((const float4*)(tin + (size_t)wrp * 128) + lane);
    float4 bgv = __ldg((const float4*)bg + lane);
    acc.x = acc.x * d2 + bgv.x;
    acc.y = acc.y * d2 + bgv.y;
    acc.z = acc.z * d2 + bgv.z;
    acc.w = acc.w * d2 + bgv.w;
    for (int e0 = beg; e0 < end; e0 += 32) {
        int e = e0 + lane;
        int s = 0; float wt = 0.f;
        if (e < end) { s = __ldg(col + e); wt = __ldg(wv + e); }
        int m = min(32, end - e0);
        for (int j = 0; j < m; j++) {
            int sj = __shfl_sync(0xffffffffu, s, j);
            float wj = __shfl_sync(0xffffffffu, wt, j);
            float4 v = __ldg((const float4*)(tin + (size_t)sj * 128) + lane);
            acc.x += v.x * wj; acc.y += v.y * wj;
            acc.z += v.z * wj; acc.w += v.w * wj;
        }
    }
    ((float4*)(out + (size_t)wrp * 128))[lane] = acc;
}

// padded-48 input -> width-47 output
__global__ void __launch_bounds__(256)
gat48(const float* __restrict__ tin, const int* __restrict__ rowptr,
      const int* __restrict__ col, const float* __restrict__ wv,
      const float* __restrict__ dinv, const float* __restrict__ bg,
      float* __restrict__ out, int n) {
    int wrp = (blockIdx.x * blockDim.x + threadIdx.x) >> 5;
    int lane = threadIdx.x & 31;
    if (wrp >= n) return;
    int beg = __ldg(rowptr + wrp), end = __ldg(rowptr + wrp + 1);
    float dv = __ldg(dinv + wrp);
    float d2 = dv * dv;
    float4 acc = make_float4(0.f, 0.f, 0.f, 0.f);
    if (lane < 12) {
        acc = __ldg((const float4*)(tin + (size_t)wrp * 48) + lane);
        acc.x *= d2; acc.y *= d2; acc.z *= d2; acc.w *= d2;
        int f = lane * 4;
        acc.x += __ldg(bg + f);
        acc.y += (f + 1 < 47) ? __ldg(bg + f + 1) : 0.f;
        acc.z += (f + 2 < 47) ? __ldg(bg + f + 2) : 0.f;
        acc.w += (f + 3 < 47) ? __ldg(bg + f + 3) : 0.f;
    }
    for (int e0 = beg; e0 < end; e0 += 32) {
        int e = e0 + lane;
        int s = 0; float wt = 0.f;
        if (e < end) { s = __ldg(col + e); wt = __ldg(wv + e); }
        int m = min(32, end - e0);
        for (int j = 0; j < m; j++) {
            int sj = __shfl_sync(0xffffffffu, s, j);
            float wj = __shfl_sync(0xffffffffu, wt, j);
            if (lane < 12) {
                float4 v = __ldg((const float4*)(tin + (size_t)sj * 48) + lane);
                acc.x += v.x * wj; acc.y += v.y * wj;
                acc.z += v.z * wj; acc.w += v.w * wj;
            }
        }
    }
    if (lane < 12) {
        int f = lane * 4;
        float* o = out + (size_t)wrp * 47;
        o[f] = acc.x;
        if (f + 1 < 47) o[f + 1] = acc.y;
        if (f + 2 < 47) o[f + 2] = acc.z;
        if (f + 3 < 47) o[f + 3] = acc.w;
    }
}

// ---------------- launch ----------------
extern "C" void kernel_launch(void* const* d_in, const int* in_sizes, int n_in,
                              void* d_out, int out_size) {
    const float* x  = (const float*)d_in[0];
    const int*   ei = (const int*)d_in[1];
    const int N = in_sizes[0] / FEAT;
    const int E = in_sizes[1] / 2;
    const int* e_src = ei;
    const int* e_dst = ei + E;

    const float* P[21];
    for (int i = 0; i < 21; i++) P[i] = (const float*)d_in[2 + i];

    float *t, *h1, *h2, *wvp, *dinv;
    int *counts, *psum, *bsum, *boff, *rowptr, *cursor, *colp;
    __nv_bfloat16 *w0hi, *w0lo, *w1hi, *w1lo, *w2hi, *w2lo;
    cudaGetSymbolAddress((void**)&t,      g_t);
    cudaGetSymbolAddress((void**)&h1,     g_h1);
    cudaGetSymbolAddress((void**)&h2,     g_h2);
    cudaGetSymbolAddress((void**)&counts, g_counts);
    cudaGetSymbolAddress((void**)&psum,   g_psum);
    cudaGetSymbolAddress((void**)&bsum,   g_bsum);
    cudaGetSymbolAddress((void**)&boff,   g_boff);
    cudaGetSymbolAddress((void**)&rowptr, g_rowptr);
    cudaGetSymbolAddress((void**)&cursor, g_cursor);
    cudaGetSymbolAddress((void**)&colp,   g_col);
    cudaGetSymbolAddress((void**)&wvp,    g_wv);
    cudaGetSymbolAddress((void**)&dinv,   g_dinv);
    cudaGetSymbolAddress((void**)&w0hi, g_w0hi);
    cudaGetSymbolAddress((void**)&w0lo, g_w0lo);
    cudaGetSymbolAddress((void**)&w1hi, g_w1hi);
    cudaGetSymbolAddress((void**)&w1lo, g_w1lo);
    cudaGetSymbolAddress((void**)&w2hi, g_w2hi);
    cudaGetSymbolAddress((void**)&w2lo, g_w2lo);
    float* out = (float*)d_out;

    // ---- CSR build ----
    const int NB = (N + 1023) / 1024;
    zero_counts<<<(N + 255) / 256, 256>>>(counts, N);
    hist_kernel<<<(E + 255) / 256, 256>>>(e_dst, counts, E);
    scan_partial<<<NB, 1024>>>(counts, psum, bsum, N);
    scan_tops<<<1, 128>>>(bsum, boff, NB);
    scan_final<<<(N + 256) / 256, 256>>>(psum, boff, counts, rowptr, cursor, dinv, N, E);
    scatter_kernel<<<(E + 255) / 256, 256>>>(e_src, e_dst, dinv, cursor, colp, wvp, E);

    // ---- weight pre-split ----
    wt_split<<<(640 * 128 + 255) / 256, 256>>>(P[2],  P[4],  w0hi, w0lo, 128, 128, 128);
    wt_split<<<(640 * 128 + 255) / 256, 256>>>(P[9],  P[11], w1hi, w1lo, 128, 128, 128);
    wt_split<<<(1920 * 64 + 255) / 256, 256>>>(P[16], P[18], w2hi, w2lo, 384, 47, 64);

    const int SM01 = (2 * 128 + 2 * 128) * 144;  // 73728 B
    const int SM2  = (2 * 128 + 2 * 64)  * 144;  // 55296 B
    cudaFuncSetAttribute(fkan4<128, 128, 128, 128>,
                         cudaFuncAttributeMaxDynamicSharedMemorySize, SM01);
    cudaFuncSetAttribute(fkan4<384, 47, 64, 48>,
                         cudaFuncAttributeMaxDynamicSharedMemorySize, SM2);

    const int GB = (N + 127) / 128;
    const int GW = ((size_t)N * 32 + 255) / 256;

    // ---- layer 0
    fkan4<128, 128, 128, 128><<<GB, 256, SM01>>>(
        x, nullptr, nullptr, P[0], P[1], w0hi, w0lo, P[3], P[5], t, N);
    gat128<<<GW, 256>>>(t, rowptr, colp, wvp, dinv, P[6], h1, N);

    // ---- layer 1
    fkan4<128, 128, 128, 128><<<GB, 256, SM01>>>(
        h1, nullptr, nullptr, P[7], P[8], w1hi, w1lo, P[10], P[12], t, N);
    gat128<<<GW, 256>>>(t, rowptr, colp, wvp, dinv, P[13], h2, N);

    // ---- layer 2 (concat input, padded out width 48 -> final 47)
    fkan4<384, 47, 64, 48><<<GB, 256, SM2>>>(
        x, h1, h2, P[14], P[15], w2hi, w2lo, P[17], P[19], t, N);
    gat48<<<GW, 256>>>(t, rowptr, colp, wvp, dinv, P[20], out, N);
}

// round 14
// speedup vs baseline: 2.9403x; 1.0928x over previous
#include <cuda_runtime.h>
#include <cuda_bf16.h>
#include <math.h>
#include <stdint.h>

#define NN 100000
#define EE 1600000
#define FEAT 128

// ---------------- scratch (device globals; allocation-free) ----------------
__device__ __align__(16) float g_t[NN * 128];
__device__ __align__(16) float g_h1[NN * 128];
__device__ __align__(16) float g_h2[NN * 128];
// CSR build
__device__ __align__(16) int   g_counts[NN];
__device__ __align__(16) int   g_psum[NN];
__device__ __align__(16) int   g_bsum[128];
__device__ __align__(16) int   g_boff[128];
__device__ __align__(16) int   g_rowptr[NN + 1];
__device__ __align__(16) int   g_cursor[NN];
__device__ __align__(16) int   g_col[EE];
__device__ __align__(16) float g_wv[EE];
__device__ __align__(16) float g_dinv[NN];
// pre-split, chunk-contiguous k-major weights: [chunk][n][64] bf16
__device__ __align__(16) __nv_bfloat16 g_w0hi[640 * 128], g_w0lo[640 * 128];
__device__ __align__(16) __nv_bfloat16 g_w1hi[640 * 128], g_w1lo[640 * 128];
__device__ __align__(16) __nv_bfloat16 g_w2hi[1920 * 64], g_w2lo[1920 * 64];

// ---------------- mma/ldmatrix helpers (baseline PTX, sm_80+) ----------------
__device__ __forceinline__ uint32_t smem_u32(const void* p) {
    uint32_t a;
    asm("{ .reg .u64 t; cvta.to.shared.u64 t, %1; cvt.u32.u64 %0, t; }" : "=r"(a) : "l"(p));
    return a;
}
__device__ __forceinline__ void ldmx4(uint32_t* r, uint32_t addr) {
    asm volatile("ldmatrix.sync.aligned.m8n8.x4.shared.b16 {%0,%1,%2,%3}, [%4];"
                 : "=r"(r[0]), "=r"(r[1]), "=r"(r[2]), "=r"(r[3]) : "r"(addr));
}
__device__ __forceinline__ void ldmx2(uint32_t* r, uint32_t addr) {
    asm volatile("ldmatrix.sync.aligned.m8n8.x2.shared.b16 {%0,%1}, [%2];"
                 : "=r"(r[0]), "=r"(r[1]) : "r"(addr));
}
__device__ __forceinline__ void mma16816(float* c, const uint32_t* a, const uint32_t* b) {
    asm volatile("mma.sync.aligned.m16n8k16.row.col.f32.bf16.bf16.f32 "
                 "{%0,%1,%2,%3}, {%4,%5,%6,%7}, {%8,%9}, {%0,%1,%2,%3};"
                 : "+f"(c[0]), "+f"(c[1]), "+f"(c[2]), "+f"(c[3])
                 : "r"(a[0]), "r"(a[1]), "r"(a[2]), "r"(a[3]), "r"(b[0]), "r"(b[1]));
}

// ---------------- CSR build ----------------
__global__ void zero_counts(int* c, int n) {
    int i = blockIdx.x * blockDim.x + threadIdx.x;
    if (i < n) c[i] = 0;
}
__global__ void hist_kernel(const int* __restrict__ dst, int* c, int E) {
    int e = blockIdx.x * blockDim.x + threadIdx.x;
    if (e < E) atomicAdd(&c[dst[e]], 1);
}
__global__ void scan_partial(const int* __restrict__ counts, int* psum, int* bsum, int n) {
    __shared__ int s[1024];
    int t = threadIdx.x, b = blockIdx.x;
    int i = b * 1024 + t;
    int v = (i < n) ? counts[i] : 0;
    s[t] = v;
    __syncthreads();
    for (int off = 1; off < 1024; off <<= 1) {
        int x = (t >= off) ? s[t - off] : 0;
        __syncthreads();
        s[t] += x;
        __syncthreads();
    }
    if (i < n) psum[i] = s[t] - v;           // exclusive
    if (t == 1023) bsum[b] = s[1023];
}
__global__ void scan_tops(const int* __restrict__ bsum, int* boff, int nb) {
    __shared__ int s[128];
    int t = threadIdx.x;
    int v = (t < nb) ? bsum[t] : 0;
    s[t] = v;
    __syncthreads();
    for (int off = 1; off < 128; off <<= 1) {
        int x = (t >= off) ? s[t - off] : 0;
        __syncthreads();
        s[t] += x;
        __syncthreads();
    }
    if (t < nb) boff[t] = s[t] - v;          // exclusive
}
__global__ void scan_final(const int* __restrict__ psum, const int* __restrict__ boff,
                           const int* __restrict__ counts,
                           int* rowptr, int* cursor, float* dinv, int n, int E) {
    int i = blockIdx.x * blockDim.x + threadIdx.x;
    if (i < n) {
        int v = psum[i] + boff[i >> 10];
        rowptr[i] = v;
        cursor[i] = v;
        dinv[i] = rsqrtf((float)(counts[i] + 1));   // +1 self loop
    } else if (i == n) {
        rowptr[n] = E;
    }
}
__global__ void scatter_kernel(const int* __restrict__ src, const int* __restrict__ dst,
                               const float* __restrict__ dinv,
                               int* cursor, int* col, float* wv, int E) {
    int e = blockIdx.x * blockDim.x + threadIdx.x;
    if (e >= E) return;
    int d = dst[e], s = src[e];
    int p = atomicAdd(&cursor[d], 1);
    col[p] = s;
    wv[p] = __ldg(dinv + s) * __ldg(dinv + d);
}

// ---------------- weight split/transpose ----------------
__global__ void wt_split(const float* __restrict__ Ws, const float* __restrict__ Wb,
                         __nv_bfloat16* __restrict__ Whi, __nv_bfloat16* __restrict__ Wlo,
                         int DIN, int DOUT, int BN) {
    int idx = blockIdx.x * blockDim.x + threadIdx.x;
    int tot = DIN * 5 * BN;
    if (idx >= tot) return;
    int kl = idx & 63;
    int rest = idx >> 6;
    int n = rest % BN;
    int c = rest / BN;
    int k = c * 64 + kl;
    float v = 0.f;
    if (n < DOUT) {
        if (k < 4 * DIN) { int d = k >> 2, g = k & 3; v = Ws[(size_t)n * (DIN * 4) + d * 4 + g]; }
        else             { v = Wb[(size_t)n * DIN + (k - 4 * DIN)]; }
    }
    __nv_bfloat16 hi = __float2bfloat16_rn(v);
    float lo = v - __bfloat162float(hi);
    size_t o = (size_t)c * BN * 64 + (size_t)n * 64 + kl;
    Whi[o] = hi;
    Wlo[o] = __float2bfloat16_rn(lo);
}

// ---------------- input loader (layer 2 = concat [x|h1|h2]) ----------------
template <int DIN>
__device__ __forceinline__ float4 loadX4(const float* __restrict__ X0,
                                         const float* __restrict__ X1,
                                         const float* __restrict__ X2,
                                         int r, int d) {
    if constexpr (DIN == 384) {
        if (d < 128)      return *(const float4*)(X0 + (size_t)r * 128 + d);
        else if (d < 256) return *(const float4*)(X1 + (size_t)r * 128 + (d - 128));
        else              return *(const float4*)(X2 + (size_t)r * 128 + (d - 256));
    } else {
        return *(const float4*)(X0 + (size_t)r * DIN + d);
    }
}

// pack 4 floats -> bf16 hi uint2 + bf16 lo uint2 (bf16x2 cvt; hi recovered by masking)
__device__ __forceinline__ void pack4(char* hibase, char* lobase, uint32_t off,
                                      float v0, float v1, float v2, float v3) {
    uint32_t h01, h23;
    asm("cvt.rn.bf16x2.f32 %0, %1, %2;" : "=r"(h01) : "f"(v1), "f"(v0));
    asm("cvt.rn.bf16x2.f32 %0, %1, %2;" : "=r"(h23) : "f"(v3), "f"(v2));
    *(uint2*)(hibase + off) = make_uint2(h01, h23);
    float f0 = __uint_as_float(h01 << 16);
    float f1 = __uint_as_float(h01 & 0xffff0000u);
    float f2 = __uint_as_float(h23 << 16);
    float f3 = __uint_as_float(h23 & 0xffff0000u);
    uint32_t l01, l23;
    asm("cvt.rn.bf16x2.f32 %0, %1, %2;" : "=r"(l01) : "f"(v1 - f1), "f"(v0 - f0));
    asm("cvt.rn.bf16x2.f32 %0, %1, %2;" : "=r"(l23) : "f"(v3 - f3), "f"(v2 - f2));
    *(uint2*)(lobase + off) = make_uint2(l01, l23);
}

// ---------------- fused FastKAN layer (mma.sync bf16 hi/lo) ----------------
template <int DIN, int DOUT, int BN, int OUTS>
__global__ void __launch_bounds__(256)
fkan4(const float* __restrict__ X0, const float* __restrict__ X1,
      const float* __restrict__ X2,
      const float* __restrict__ gam, const float* __restrict__ bet,
      const __nv_bfloat16* __restrict__ WhiG, const __nv_bfloat16* __restrict__ WloG,
      const float* __restrict__ bs, const float* __restrict__ bb,
      float* __restrict__ out_t, int nrows) {
    constexpr int BM = 128;
    constexpr int PK = 72;
    constexpr int AROWB = PK * 2;           // 144 bytes
    constexpr int CRBF = DIN / 16;
    constexpr int CTOT = DIN * 5 / 64;
    constexpr int NT_ = BN / 16;

    extern __shared__ char sm[];
    char* AHc = sm;
    char* ALc = sm + BM * AROWB;
    char* WHc = sm + 2 * BM * AROWB;
    char* WLc = WHc + BN * AROWB;
    __shared__ float sMu[BM], sRs[BM];

    const int t = threadIdx.x;
    const int wid = t >> 5;
    const int lane = t & 31;
    const int row0 = blockIdx.x * BM;
    const uint32_t sbase = smem_u32(sm);
    const uint32_t aAH = sbase;
    const uint32_t aWH = sbase + 2 * BM * AROWB;

    for (int n = wid; n < BM; n += 8) {
        int r = row0 + n;
        float s = 0.f, ss = 0.f;
        if (r < nrows) {
            for (int d4 = lane; d4 < DIN / 4; d4 += 32) {
                float4 v = loadX4<DIN>(X0, X1, X2, r, d4 * 4);
                s  += v.x + v.y + v.z + v.w;
                ss += v.x * v.x + v.y * v.y + v.z * v.z + v.w * v.w;
            }
        }
        #pragma unroll
        for (int off = 16; off; off >>= 1) {
            s  += __shfl_xor_sync(0xffffffffu, s,  off);
            ss += __shfl_xor_sync(0xffffffffu, ss, off);
        }
        if (lane == 0) {
            if (r < nrows) {
                float mu = s * (1.0f / DIN);
                float var = ss * (1.0f / DIN) - mu * mu;
                sMu[n] = mu; sRs[n] = rsqrtf(var + 1e-5f);
            } else { sMu[n] = 0.f; sRs[n] = 0.f; }
        }
    }
    __syncthreads();

    float acc[2][NT_][4];
    #pragma unroll
    for (int mt = 0; mt < 2; mt++)
        #pragma unroll
        for (int nt = 0; nt < NT_; nt++)
            #pragma unroll
            for (int j = 0; j < 4; j++) acc[mt][nt][j] = 0.f;

    const int wr = (wid >> 1) * 32;
    const int wc = (wid & 1) * (BN / 2);
    const int am = wr + (lane & 15);
    const int akh = lane >> 4;
    const int bnr = lane & 7;
    const int bkh = (lane >> 3) & 1;

    const float GR[4] = {-2.0f, -2.0f / 3.0f, 2.0f / 3.0f, 2.0f};

    for (int c = 0; c < CTOT; ++c) {
        if (c < CRBF) {
            for (int p = t; p < BM * 4; p += 256) {
                int n = p >> 2, q = p & 3;
                int d = c * 16 + q * 4;
                int r = row0 + n;
                float4 xv = make_float4(0.f, 0.f, 0.f, 0.f);
                if (r < nrows) xv = loadX4<DIN>(X0, X1, X2, r, d);
                float4 gv = *(const float4*)(gam + d);
                float4 bv = *(const float4*)(bet + d);
                float mu = sMu[n], rs = sRs[n];
                float xs[4] = {xv.x, xv.y, xv.z, xv.w};
                float gs[4] = {gv.x, gv.y, gv.z, gv.w};
                float bs4[4] = {bv.x, bv.y, bv.z, bv.w};
                #pragma unroll
                for (int j = 0; j < 4; j++) {
                    float z = (xs[j] - mu) * rs * gs[j] + bs4[j];
                    float u0 = (z - GR[0]) * 0.75f;
                    float u1 = (z - GR[1]) * 0.75f;
                    float u2 = (z - GR[2]) * 0.75f;
                    float u3 = (z - GR[3]) * 0.75f;
                    uint32_t off = (uint32_t)n * AROWB + (uint32_t)(q * 4 + j) * 8;
                    pack4(AHc, ALc, off, __expf(-u0 * u0), __expf(-u1 * u1),
                          __expf(-u2 * u2), __expf(-u3 * u3));
                }
            }
        } else {
            int ds0 = (c - CRBF) * 64;
            for (int p = t; p < BM * 16; p += 256) {
                int n = p >> 4, q = p & 15;
                int d = ds0 + q * 4;
                int r = row0 + n;
                float4 xv = make_float4(0.f, 0.f, 0.f, 0.f);
                if (r < nrows) xv = loadX4<DIN>(X0, X1, X2, r, d);
                float s0 = xv.x * __fdividef(1.0f, 1.0f + __expf(-xv.x));
                float s1 = xv.y * __fdividef(1.0f, 1.0f + __expf(-xv.y));
                float s2 = xv.z * __fdividef(1.0f, 1.0f + __expf(-xv.z));
                float s3 = xv.w * __fdividef(1.0f, 1.0f + __expf(-xv.w));
                uint32_t off = (uint32_t)n * AROWB + (uint32_t)q * 8;
                pack4(AHc, ALc, off, s0, s1, s2, s3);
            }
        }
        {
            const uint4* sh = (const uint4*)(WhiG + (size_t)c * BN * 64);
            const uint4* sl = (const uint4*)(WloG + (size_t)c * BN * 64);
            for (int p = t; p < BN * 8; p += 256) {
                int n = p >> 3, i = p & 7;
                *(uint4*)(WHc + n * AROWB + i * 16) = sh[n * 8 + i];
                *(uint4*)(WLc + n * AROWB + i * 16) = sl[n * 8 + i];
            }
        }
        __syncthreads();

        #pragma unroll
        for (int ks = 0; ks < 4; ks++) {
            uint32_t ahi[2][4], alo[2][4], bhi[NT_][2], blo[NT_][2];
            #pragma unroll
            for (int mt = 0; mt < 2; mt++) {
                uint32_t ad = aAH + (uint32_t)(am + mt * 16) * AROWB + ks * 32 + akh * 16;
                ldmx4(ahi[mt], ad);
                ldmx4(alo[mt], ad + (uint32_t)BM * AROWB);
            }
            #pragma unroll
            for (int nt = 0; nt < NT_; nt++) {
                uint32_t bd = aWH + (uint32_t)(wc + nt * 8 + bnr) * AROWB + ks * 32 + bkh * 16;
                ldmx2(bhi[nt], bd);
                ldmx2(blo[nt], bd + (uint32_t)BN * AROWB);
            }
            #pragma unroll
            for (int mt = 0; mt < 2; mt++)
                #pragma unroll
                for (int nt = 0; nt < NT_; nt++) {
                    mma16816(acc[mt][nt], ahi[mt], bhi[nt]);
                    mma16816(acc[mt][nt], ahi[mt], blo[nt]);
                    mma16816(acc[mt][nt], alo[mt], bhi[nt]);
                }
        }
        __syncthreads();
    }

    // ---- epilogue: biases only (self-loop/bias handled by gather) ----
    const int rb = row0 + wr + (lane >> 2);
    const int cb = wc + (lane & 3) * 2;
    #pragma unroll
    for (int mt = 0; mt < 2; mt++) {
        #pragma unroll
        for (int h = 0; h < 2; h++) {
            int r = rb + mt * 16 + h * 8;
            if (r >= nrows) continue;
            #pragma unroll
            for (int nt = 0; nt < NT_; nt++) {
                int o = cb + nt * 8;
                if (o >= OUTS) continue;
                float a0 = acc[mt][nt][h * 2 + 0];
                float a1 = acc[mt][nt][h * 2 + 1];
                float v0 = (o < DOUT)     ? a0 + __ldg(bs + o)     + __ldg(bb + o)     : 0.f;
                float v1 = (o + 1 < DOUT) ? a1 + __ldg(bs + o + 1) + __ldg(bb + o + 1) : 0.f;
                *(float2*)(out_t + (size_t)r * OUTS + o) = make_float2(v0, v1);
            }
        }
    }
}

// ---------------- CSR gather aggregation ----------------
__global__ void __launch_bounds__(256)
gat128(const float* __restrict__ tin, const int* __restrict__ rowptr,
       const int* __restrict__ col, const float* __restrict__ wv,
       const float* __restrict__ dinv, const float* __restrict__ bg,
       float* __restrict__ out, int n) {
    int wrp = (blockIdx.x * blockDim.x + threadIdx.x) >> 5;
    int lane = threadIdx.x & 31;
    if (wrp >= n) return;
    int beg = __ldg(rowptr + wrp), end = __ldg(rowptr + wrp + 1);
    float dv = __ldg(dinv + wrp);
    float d2 = dv * dv;
    float4 acc = __ldg((const float4*)(tin + (size_t)wrp * 128) + lane);
    float4 bgv = __ldg((const float4*)bg + lane);
    acc.x = acc.x * d2 + bgv.x;
    acc.y = acc.y * d2 + bgv.y;
    acc.z = acc.z * d2 + bgv.z;
    acc.w = acc.w * d2 + bgv.w;
    for (int e0 = beg; e0 < end; e0 += 32) {
        int e = e0 + lane;
        int s = 0; float wt = 0.f;
        if (e < end) { s = __ldg(col + e); wt = __ldg(wv + e); }
        int m = min(32, end - e0);
        int j = 0;
        for (; j + 4 <= m; j += 4) {
            int s0 = __shfl_sync(0xffffffffu, s, j + 0);
            int s1 = __shfl_sync(0xffffffffu, s, j + 1);
            int s2 = __shfl_sync(0xffffffffu, s, j + 2);
            int s3 = __shfl_sync(0xffffffffu, s, j + 3);
            float w0 = __shfl_sync(0xffffffffu, wt, j + 0);
            float w1 = __shfl_sync(0xffffffffu, wt, j + 1);
            float w2 = __shfl_sync(0xffffffffu, wt, j + 2);
            float w3 = __shfl_sync(0xffffffffu, wt, j + 3);
            float4 v0 = __ldg((const float4*)(tin + (size_t)s0 * 128) + lane);
            float4 v1 = __ldg((const float4*)(tin + (size_t)s1 * 128) + lane);
            float4 v2 = __ldg((const float4*)(tin + (size_t)s2 * 128) + lane);
            float4 v3 = __ldg((const float4*)(tin + (size_t)s3 * 128) + lane);
            acc.x += v0.x * w0 + v1.x * w1 + v2.x * w2 + v3.x * w3;
            acc.y += v0.y * w0 + v1.y * w1 + v2.y * w2 + v3.y * w3;
            acc.z += v0.z * w0 + v1.z * w1 + v2.z * w2 + v3.z * w3;
            acc.w += v0.w * w0 + v1.w * w1 + v2.w * w2 + v3.w * w3;
        }
        for (; j < m; j++) {
            int sj = __shfl_sync(0xffffffffu, s, j);
            float wj = __shfl_sync(0xffffffffu, wt, j);
            float4 v = __ldg((const float4*)(tin + (size_t)sj * 128) + lane);
            acc.x += v.x * wj; acc.y += v.y * wj;
            acc.z += v.z * wj; acc.w += v.w * wj;
        }
    }
    ((float4*)(out + (size_t)wrp * 128))[lane] = acc;
}

// padded-48 input -> width-47 output
__global__ void __launch_bounds__(256)
gat48(const float* __restrict__ tin, const int* __restrict__ rowptr,
      const int* __restrict__ col, const float* __restrict__ wv,
      const float* __restrict__ dinv, const float* __restrict__ bg,
      float* __restrict__ out, int n) {
    int wrp = (blockIdx.x * blockDim.x + threadIdx.x) >> 5;
    int lane = threadIdx.x & 31;
    if (wrp >= n) return;
    int beg = __ldg(rowptr + wrp), end = __ldg(rowptr + wrp + 1);
    float dv = __ldg(dinv + wrp);
    float d2 = dv * dv;
    float4 acc = make_float4(0.f, 0.f, 0.f, 0.f);
    if (lane < 12) {
        acc = __ldg((const float4*)(tin + (size_t)wrp * 48) + lane);
        acc.x *= d2; acc.y *= d2; acc.z *= d2; acc.w *= d2;
        int f = lane * 4;
        acc.x += __ldg(bg + f);
        acc.y += (f + 1 < 47) ? __ldg(bg + f + 1) : 0.f;
        acc.z += (f + 2 < 47) ? __ldg(bg + f + 2) : 0.f;
        acc.w += (f + 3 < 47) ? __ldg(bg + f + 3) : 0.f;
    }
    for (int e0 = beg; e0 < end; e0 += 32) {
        int e = e0 + lane;
        int s = 0; float wt = 0.f;
        if (e < end) { s = __ldg(col + e); wt = __ldg(wv + e); }
        int m = min(32, end - e0);
        int j = 0;
        for (; j + 2 <= m; j += 2) {
            int s0 = __shfl_sync(0xffffffffu, s, j + 0);
            int s1 = __shfl_sync(0xffffffffu, s, j + 1);
            float w0 = __shfl_sync(0xffffffffu, wt, j + 0);
            float w1 = __shfl_sync(0xffffffffu, wt, j + 1);
            if (lane < 12) {
                float4 v0 = __ldg((const float4*)(tin + (size_t)s0 * 48) + lane);
                float4 v1 = __ldg((const float4*)(tin + (size_t)s1 * 48) + lane);
                acc.x += v0.x * w0 + v1.x * w1;
                acc.y += v0.y * w0 + v1.y * w1;
                acc.z += v0.z * w0 + v1.z * w1;
                acc.w += v0.w * w0 + v1.w * w1;
            }
        }
        for (; j < m; j++) {
            int sj = __shfl_sync(0xffffffffu, s, j);
            float wj = __shfl_sync(0xffffffffu, wt, j);
            if (lane < 12) {
                float4 v = __ldg((const float4*)(tin + (size_t)sj * 48) + lane);
                acc.x += v.x * wj; acc.y += v.y * wj;
                acc.z += v.z * wj; acc.w += v.w * wj;
            }
        }
    }
    if (lane < 12) {
        int f = lane * 4;
        float* o = out + (size_t)wrp * 47;
        o[f] = acc.x;
        if (f + 1 < 47) o[f + 1] = acc.y;
        if (f + 2 < 47) o[f + 2] = acc.z;
        if (f + 3 < 47) o[f + 3] = acc.w;
    }
}

// ---------------- launch ----------------
extern "C" void kernel_launch(void* const* d_in, const int* in_sizes, int n_in,
                              void* d_out, int out_size) {
    const float* x  = (const float*)d_in[0];
    const int*   ei = (const int*)d_in[1];
    const int N = in_sizes[0] / FEAT;
    const int E = in_sizes[1] / 2;
    const int* e_src = ei;
    const int* e_dst = ei + E;

    const float* P[21];
    for (int i = 0; i < 21; i++) P[i] = (const float*)d_in[2 + i];

    float *t, *h1, *h2, *wvp, *dinv;
    int *counts, *psum, *bsum, *boff, *rowptr, *cursor, *colp;
    __nv_bfloat16 *w0hi, *w0lo, *w1hi, *w1lo, *w2hi, *w2lo;
    cudaGetSymbolAddress((void**)&t,      g_t);
    cudaGetSymbolAddress((void**)&h1,     g_h1);
    cudaGetSymbolAddress((void**)&h2,     g_h2);
    cudaGetSymbolAddress((void**)&counts, g_counts);
    cudaGetSymbolAddress((void**)&psum,   g_psum);
    cudaGetSymbolAddress((void**)&bsum,   g_bsum);
    cudaGetSymbolAddress((void**)&boff,   g_boff);
    cudaGetSymbolAddress((void**)&rowptr, g_rowptr);
    cudaGetSymbolAddress((void**)&cursor, g_cursor);
    cudaGetSymbolAddress((void**)&colp,   g_col);
    cudaGetSymbolAddress((void**)&wvp,    g_wv);
    cudaGetSymbolAddress((void**)&dinv,   g_dinv);
    cudaGetSymbolAddress((void**)&w0hi, g_w0hi);
    cudaGetSymbolAddress((void**)&w0lo, g_w0lo);
    cudaGetSymbolAddress((void**)&w1hi, g_w1hi);
    cudaGetSymbolAddress((void**)&w1lo, g_w1lo);
    cudaGetSymbolAddress((void**)&w2hi, g_w2hi);
    cudaGetSymbolAddress((void**)&w2lo, g_w2lo);
    float* out = (float*)d_out;

    const int SM01 = (2 * 128 + 2 * 128) * 144;  // 73728 B
    const int SM2  = (2 * 128 + 2 * 64)  * 144;  // 55296 B
    cudaFuncSetAttribute(fkan4<128, 128, 128, 128>,
                         cudaFuncAttributeMaxDynamicSharedMemorySize, SM01);
    cudaFuncSetAttribute(fkan4<384, 47, 64, 48>,
                         cudaFuncAttributeMaxDynamicSharedMemorySize, SM2);

    const int GB = (N + 127) / 128;
    const int GW = ((size_t)N * 32 + 255) / 256;
    const int NB = (N + 1023) / 1024;

    // launches 1-5: weight prep + CSR start (fkan0 is 6th launch -> ncu -s 5 -c 1)
    wt_split<<<(640 * 128 + 255) / 256, 256>>>(P[2],  P[4],  w0hi, w0lo, 128, 128, 128);
    wt_split<<<(640 * 128 + 255) / 256, 256>>>(P[9],  P[11], w1hi, w1lo, 128, 128, 128);
    wt_split<<<(1920 * 64 + 255) / 256, 256>>>(P[16], P[18], w2hi, w2lo, 384, 47, 64);
    zero_counts<<<(N + 255) / 256, 256>>>(counts, N);
    hist_kernel<<<(E + 255) / 256, 256>>>(e_dst, counts, E);

    // ---- layer 0 FKAN (independent of CSR)
    fkan4<128, 128, 128, 128><<<GB, 256, SM01>>>(
        x, nullptr, nullptr, P[0], P[1], w0hi, w0lo, P[3], P[5], t, N);

    // ---- finish CSR build
    scan_partial<<<NB, 1024>>>(counts, psum, bsum, N);
    scan_tops<<<1, 128>>>(bsum, boff, NB);
    scan_final<<<(N + 256) / 256, 256>>>(psum, boff, counts, rowptr, cursor, dinv, N, E);
    scatter_kernel<<<(E + 255) / 256, 256>>>(e_src, e_dst, dinv, cursor, colp, wvp, E);

    gat128<<<GW, 256>>>(t, rowptr, colp, wvp, dinv, P[6], h1, N);

    // ---- layer 1
    fkan4<128, 128, 128, 128><<<GB, 256, SM01>>>(
        h1, nullptr, nullptr, P[7], P[8], w1hi, w1lo, P[10], P[12], t, N);
    gat128<<<GW, 256>>>(t, rowptr, colp, wvp, dinv, P[13], h2, N);

    // ---- layer 2 (concat input, padded out width 48 -> final 47)
    fkan4<384, 47, 64, 48><<<GB, 256, SM2>>>(
        x, h1, h2, P[14], P[15], w2hi, w2lo, P[17], P[19], t, N);
    gat48<<<GW, 256>>>(t, rowptr, colp, wvp, dinv, P[20], out, N);
}

// round 17
// speedup vs baseline: 3.0205x; 1.0273x over previous
#include <cuda_runtime.h>
#include <cuda_bf16.h>
#include <math.h>
#include <stdint.h>

#define NN 100000
#define EE 1600000
#define FEAT 128

// ---------------- scratch (device globals; allocation-free) ----------------
__device__ __align__(16) float g_t[NN * 128];
__device__ __align__(16) float g_h1[NN * 128];
__device__ __align__(16) float g_h2[NN * 128];
// CSR build
__device__ __align__(16) int   g_counts[NN];
__device__ __align__(16) int   g_psum[NN];
__device__ __align__(16) int   g_bsum[128];
__device__ __align__(16) int   g_boff[128];
__device__ __align__(16) int   g_rowptr[NN + 1];
__device__ __align__(16) int   g_cursor[NN];
__device__ __align__(16) int   g_col[EE];
__device__ __align__(16) float g_wv[EE];
__device__ __align__(16) float g_dinv[NN];
// pre-split, chunk-contiguous k-major weights: [chunk][n][64] bf16
__device__ __align__(16) __nv_bfloat16 g_w0hi[640 * 128], g_w0lo[640 * 128];
__device__ __align__(16) __nv_bfloat16 g_w1hi[640 * 128], g_w1lo[640 * 128];
__device__ __align__(16) __nv_bfloat16 g_w2hi[1920 * 64], g_w2lo[1920 * 64];

// ---------------- mma/ldmatrix/cp.async helpers (baseline PTX, sm_80+) -----
__device__ __forceinline__ uint32_t smem_u32(const void* p) {
    uint32_t a;
    asm("{ .reg .u64 t; cvta.to.shared.u64 t, %1; cvt.u32.u64 %0, t; }" : "=r"(a) : "l"(p));
    return a;
}
__device__ __forceinline__ void ldmx4(uint32_t* r, uint32_t addr) {
    asm volatile("ldmatrix.sync.aligned.m8n8.x4.shared.b16 {%0,%1,%2,%3}, [%4];"
                 : "=r"(r[0]), "=r"(r[1]), "=r"(r[2]), "=r"(r[3]) : "r"(addr));
}
__device__ __forceinline__ void mma16816(float* c, const uint32_t* a, const uint32_t* b) {
    asm volatile("mma.sync.aligned.m16n8k16.row.col.f32.bf16.bf16.f32 "
                 "{%0,%1,%2,%3}, {%4,%5,%6,%7}, {%8,%9}, {%0,%1,%2,%3};"
                 : "+f"(c[0]), "+f"(c[1]), "+f"(c[2]), "+f"(c[3])
                 : "r"(a[0]), "r"(a[1]), "r"(a[2]), "r"(a[3]), "r"(b[0]), "r"(b[1]));
}
__device__ __forceinline__ void cp_async16(uint32_t saddr, const void* g) {
    asm volatile("cp.async.cg.shared.global [%0], [%1], 16;" :: "r"(saddr), "l"(g) : "memory");
}
__device__ __forceinline__ void cp_commit() {
    asm volatile("cp.async.commit_group;" ::: "memory");
}
__device__ __forceinline__ void cp_wait1() {
    asm volatile("cp.async.wait_group 1;" ::: "memory");
}

// ---------------- CSR build ----------------
__global__ void zero_counts(int* c, int n) {
    int i = blockIdx.x * blockDim.x + threadIdx.x;
    if (i < n) c[i] = 0;
}
__global__ void hist_kernel(const int* __restrict__ dst, int* c, int E) {
    int e = blockIdx.x * blockDim.x + threadIdx.x;
    if (e < E) atomicAdd(&c[dst[e]], 1);
}
__global__ void scan_partial(const int* __restrict__ counts, int* psum, int* bsum, int n) {
    __shared__ int s[1024];
    int t = threadIdx.x, b = blockIdx.x;
    int i = b * 1024 + t;
    int v = (i < n) ? counts[i] : 0;
    s[t] = v;
    __syncthreads();
    for (int off = 1; off < 1024; off <<= 1) {
        int x = (t >= off) ? s[t - off] : 0;
        __syncthreads();
        s[t] += x;
        __syncthreads();
    }
    if (i < n) psum[i] = s[t] - v;           // exclusive
    if (t == 1023) bsum[b] = s[1023];
}
__global__ void scan_tops(const int* __restrict__ bsum, int* boff, int nb) {
    __shared__ int s[128];
    int t = threadIdx.x;
    int v = (t < nb) ? bsum[t] : 0;
    s[t] = v;
    __syncthreads();
    for (int off = 1; off < 128; off <<= 1) {
        int x = (t >= off) ? s[t - off] : 0;
        __syncthreads();
        s[t] += x;
        __syncthreads();
    }
    if (t < nb) boff[t] = s[t] - v;          // exclusive
}
__global__ void scan_final(const int* __restrict__ psum, const int* __restrict__ boff,
                           const int* __restrict__ counts,
                           int* rowptr, int* cursor, float* dinv, int n, int E) {
    int i = blockIdx.x * blockDim.x + threadIdx.x;
    if (i < n) {
        int v = psum[i] + boff[i >> 10];
        rowptr[i] = v;
        cursor[i] = v;
        dinv[i] = rsqrtf((float)(counts[i] + 1));   // +1 self loop
    } else if (i == n) {
        rowptr[n] = E;
    }
}
__global__ void scatter_kernel(const int* __restrict__ src, const int* __restrict__ dst,
                               const float* __restrict__ dinv,
                               int* cursor, int* col, float* wv, int E) {
    int e = blockIdx.x * blockDim.x + threadIdx.x;
    if (e >= E) return;
    int d = dst[e], s = src[e];
    int p = atomicAdd(&cursor[d], 1);
    col[p] = s;
    wv[p] = __ldg(dinv + s) * __ldg(dinv + d);
}

// ---------------- weight split/transpose ----------------
__global__ void wt_split(const float* __restrict__ Ws, const float* __restrict__ Wb,
                         __nv_bfloat16* __restrict__ Whi, __nv_bfloat16* __restrict__ Wlo,
                         int DIN, int DOUT, int BN) {
    int idx = blockIdx.x * blockDim.x + threadIdx.x;
    int tot = DIN * 5 * BN;
    if (idx >= tot) return;
    int kl = idx & 63;
    int rest = idx >> 6;
    int n = rest % BN;
    int c = rest / BN;
    int k = c * 64 + kl;
    float v = 0.f;
    if (n < DOUT) {
        if (k < 4 * DIN) { int d = k >> 2, g = k & 3; v = Ws[(size_t)n * (DIN * 4) + d * 4 + g]; }
        else             { v = Wb[(size_t)n * DIN + (k - 4 * DIN)]; }
    }
    __nv_bfloat16 hi = __float2bfloat16_rn(v);
    float lo = v - __bfloat162float(hi);
    size_t o = (size_t)c * BN * 64 + (size_t)n * 64 + kl;
    Whi[o] = hi;
    Wlo[o] = __float2bfloat16_rn(lo);
}

// ---------------- input loader (layer 2 = concat [x|h1|h2]) ----------------
template <int DIN>
__device__ __forceinline__ float4 loadX4(const float* __restrict__ X0,
                                         const float* __restrict__ X1,
                                         const float* __restrict__ X2,
                                         int r, int d) {
    if constexpr (DIN == 384) {
        if (d < 128)      return *(const float4*)(X0 + (size_t)r * 128 + d);
        else if (d < 256) return *(const float4*)(X1 + (size_t)r * 128 + (d - 128));
        else              return *(const float4*)(X2 + (size_t)r * 128 + (d - 256));
    } else {
        return *(const float4*)(X0 + (size_t)r * DIN + d);
    }
}

// pack 4 floats -> bf16 hi uint2 + bf16 lo uint2 (bf16x2 cvt; hi recovered by masking)
__device__ __forceinline__ void pack4(char* hibase, char* lobase, uint32_t off,
                                      float v0, float v1, float v2, float v3) {
    uint32_t h01, h23;
    asm("cvt.rn.bf16x2.f32 %0, %1, %2;" : "=r"(h01) : "f"(v1), "f"(v0));
    asm("cvt.rn.bf16x2.f32 %0, %1, %2;" : "=r"(h23) : "f"(v3), "f"(v2));
    *(uint2*)(hibase + off) = make_uint2(h01, h23);
    float f0 = __uint_as_float(h01 << 16);
    float f1 = __uint_as_float(h01 & 0xffff0000u);
    float f2 = __uint_as_float(h23 << 16);
    float f3 = __uint_as_float(h23 & 0xffff0000u);
    uint32_t l01, l23;
    asm("cvt.rn.bf16x2.f32 %0, %1, %2;" : "=r"(l01) : "f"(v1 - f1), "f"(v0 - f0));
    asm("cvt.rn.bf16x2.f32 %0, %1, %2;" : "=r"(l23) : "f"(v3 - f3), "f"(v2 - f2));
    *(uint2*)(lobase + off) = make_uint2(l01, l23);
}

// ---------------- fused FastKAN layer (mma.sync bf16 hi/lo) ----------------
// A single-buffered; W double-buffered via cp.async (prefetch c+1 during build of c)
template <int DIN, int DOUT, int BN, int OUTS>
__global__ void __launch_bounds__(256)
fkan4(const float* __restrict__ X0, const float* __restrict__ X1,
      const float* __restrict__ X2,
      const float* __restrict__ gam, const float* __restrict__ bet,
      const __nv_bfloat16* __restrict__ WhiG, const __nv_bfloat16* __restrict__ WloG,
      const float* __restrict__ bs, const float* __restrict__ bb,
      float* __restrict__ out_t, int nrows) {
    constexpr int BM = 128;
    constexpr int PK = 72;
    constexpr int AROWB = PK * 2;            // 144 bytes
    constexpr int CRBF = DIN / 16;
    constexpr int CTOT = DIN * 5 / 64;
    constexpr int NT_ = BN / 16;
    constexpr uint32_t WBYTES = (uint32_t)BN * AROWB;
    constexpr uint32_t OFF_W = 2u * BM * AROWB;   // after A hi+lo

    extern __shared__ char sm[];
    char* AHc = sm;
    char* ALc = sm + BM * AROWB;
    __shared__ float sMu[BM], sRs[BM];

    const int t = threadIdx.x;
    const int wid = t >> 5;
    const int lane = t & 31;
    const int row0 = blockIdx.x * BM;
    const uint32_t sbase = smem_u32(sm);
    const uint32_t aAH = sbase;

    // prefetch W chunk 0
    {
        const uint4* sh = (const uint4*)WhiG;
        const uint4* sl = (const uint4*)WloG;
        uint32_t wb = sbase + OFF_W;           // buffer 0
        for (int p = t; p < BN * 8; p += 256) {
            int n = p >> 3, i = p & 7;
            uint32_t d = wb + (uint32_t)n * AROWB + (uint32_t)i * 16;
            cp_async16(d, sh + p);
            cp_async16(d + WBYTES, sl + p);
        }
        cp_commit();
    }

    for (int n = wid; n < BM; n += 8) {
        int r = row0 + n;
        float s = 0.f, ss = 0.f;
        if (r < nrows) {
            for (int d4 = lane; d4 < DIN / 4; d4 += 32) {
                float4 v = loadX4<DIN>(X0, X1, X2, r, d4 * 4);
                s  += v.x + v.y + v.z + v.w;
                ss += v.x * v.x + v.y * v.y + v.z * v.z + v.w * v.w;
            }
        }
        #pragma unroll
        for (int off = 16; off; off >>= 1) {
            s  += __shfl_xor_sync(0xffffffffu, s,  off);
            ss += __shfl_xor_sync(0xffffffffu, ss, off);
        }
        if (lane == 0) {
            if (r < nrows) {
                float mu = s * (1.0f / DIN);
                float var = ss * (1.0f / DIN) - mu * mu;
                sMu[n] = mu; sRs[n] = rsqrtf(var + 1e-5f);
            } else { sMu[n] = 0.f; sRs[n] = 0.f; }
        }
    }
    __syncthreads();

    float acc[2][NT_][4];
    #pragma unroll
    for (int mt = 0; mt < 2; mt++)
        #pragma unroll
        for (int nt = 0; nt < NT_; nt++)
            #pragma unroll
            for (int j = 0; j < 4; j++) acc[mt][nt][j] = 0.f;

    const int wr = (wid >> 1) * 32;
    const int wc = (wid & 1) * (BN / 2);
    const int am = wr + (lane & 15);
    const int akh = lane >> 4;
    const int bnr = lane & 7;
    const int bkh = (lane >> 3) & 1;
    const int btp = lane >> 4;               // tile-pair selector for B ldmx4

    const float GR[4] = {-2.0f, -2.0f / 3.0f, 2.0f / 3.0f, 2.0f};

    for (int c = 0; c < CTOT; ++c) {
        // ---- prefetch W chunk c+1 into other buffer ----
        if (c + 1 < CTOT) {
            const uint4* sh = (const uint4*)(WhiG + (size_t)(c + 1) * BN * 64);
            const uint4* sl = (const uint4*)(WloG + (size_t)(c + 1) * BN * 64);
            uint32_t wb = sbase + OFF_W + (uint32_t)((c + 1) & 1) * 2u * WBYTES;
            for (int p = t; p < BN * 8; p += 256) {
                int n = p >> 3, i = p & 7;
                uint32_t d = wb + (uint32_t)n * AROWB + (uint32_t)i * 16;
                cp_async16(d, sh + p);
                cp_async16(d + WBYTES, sl + p);
            }
        }
        cp_commit();

        // ---- build A chunk (hi/lo bf16) ----
        if (c < CRBF) {
            for (int p = t; p < BM * 4; p += 256) {
                int n = p >> 2, q = p & 3;
                int d = c * 16 + q * 4;
                int r = row0 + n;
                float4 xv = make_float4(0.f, 0.f, 0.f, 0.f);
                if (r < nrows) xv = loadX4<DIN>(X0, X1, X2, r, d);
                float4 gv = *(const float4*)(gam + d);
                float4 bv = *(const float4*)(bet + d);
                float mu = sMu[n], rs = sRs[n];
                float xs[4] = {xv.x, xv.y, xv.z, xv.w};
                float gs[4] = {gv.x, gv.y, gv.z, gv.w};
                float bs4[4] = {bv.x, bv.y, bv.z, bv.w};
                #pragma unroll
                for (int j = 0; j < 4; j++) {
                    float z = (xs[j] - mu) * rs * gs[j] + bs4[j];
                    float u0 = (z - GR[0]) * 0.75f;
                    float u1 = (z - GR[1]) * 0.75f;
                    float u2 = (z - GR[2]) * 0.75f;
                    float u3 = (z - GR[3]) * 0.75f;
                    uint32_t off = (uint32_t)n * AROWB + (uint32_t)(q * 4 + j) * 8;
                    pack4(AHc, ALc, off, __expf(-u0 * u0), __expf(-u1 * u1),
                          __expf(-u2 * u2), __expf(-u3 * u3));
                }
            }
        } else {
            int ds0 = (c - CRBF) * 64;
            for (int p = t; p < BM * 16; p += 256) {
                int n = p >> 4, q = p & 15;
                int d = ds0 + q * 4;
                int r = row0 + n;
                float4 xv = make_float4(0.f, 0.f, 0.f, 0.f);
                if (r < nrows) xv = loadX4<DIN>(X0, X1, X2, r, d);
                float s0 = xv.x * __fdividef(1.0f, 1.0f + __expf(-xv.x));
                float s1 = xv.y * __fdividef(1.0f, 1.0f + __expf(-xv.y));
                float s2 = xv.z * __fdividef(1.0f, 1.0f + __expf(-xv.z));
                float s3 = xv.w * __fdividef(1.0f, 1.0f + __expf(-xv.w));
                uint32_t off = (uint32_t)n * AROWB + (uint32_t)q * 8;
                pack4(AHc, ALc, off, s0, s1, s2, s3);
            }
        }
        cp_wait1();          // W chunk c resident
        __syncthreads();

        const uint32_t aWH = sbase + OFF_W + (uint32_t)(c & 1) * 2u * WBYTES;

        #pragma unroll
        for (int ks = 0; ks < 4; ks++) {
            uint32_t ahi[2][4], alo[2][4], bhi[NT_][2], blo[NT_][2];
            #pragma unroll
            for (int mt = 0; mt < 2; mt++) {
                uint32_t ad = aAH + (uint32_t)(am + mt * 16) * AROWB + ks * 32 + akh * 16;
                ldmx4(ahi[mt], ad);
                ldmx4(alo[mt], ad + (uint32_t)BM * AROWB);
            }
            #pragma unroll
            for (int np = 0; np < NT_ / 2; np++) {
                uint32_t bd = aWH + (uint32_t)(wc + (np * 2 + btp) * 8 + bnr) * AROWB
                              + ks * 32 + bkh * 16;
                uint32_t tmp[4];
                ldmx4(tmp, bd);
                bhi[np * 2][0] = tmp[0]; bhi[np * 2][1] = tmp[1];
                bhi[np * 2 + 1][0] = tmp[2]; bhi[np * 2 + 1][1] = tmp[3];
                ldmx4(tmp, bd + WBYTES);
                blo[np * 2][0] = tmp[0]; blo[np * 2][1] = tmp[1];
                blo[np * 2 + 1][0] = tmp[2]; blo[np * 2 + 1][1] = tmp[3];
            }
            #pragma unroll
            for (int mt = 0; mt < 2; mt++)
                #pragma unroll
                for (int nt = 0; nt < NT_; nt++) {
                    mma16816(acc[mt][nt], ahi[mt], bhi[nt]);
                    mma16816(acc[mt][nt], ahi[mt], blo[nt]);
                    mma16816(acc[mt][nt], alo[mt], bhi[nt]);
                }
        }
        __syncthreads();
    }

    // ---- epilogue: biases only (self-loop/bias handled by gather) ----
    const int rb = row0 + wr + (lane >> 2);
    const int cb = wc + (lane & 3) * 2;
    #pragma unroll
    for (int mt = 0; mt < 2; mt++) {
        #pragma unroll
        for (int h = 0; h < 2; h++) {
            int r = rb + mt * 16 + h * 8;
            if (r >= nrows) continue;
            #pragma unroll
            for (int nt = 0; nt < NT_; nt++) {
                int o = cb + nt * 8;
                if (o >= OUTS) continue;
                float a0 = acc[mt][nt][h * 2 + 0];
                float a1 = acc[mt][nt][h * 2 + 1];
                float v0 = (o < DOUT)     ? a0 + __ldg(bs + o)     + __ldg(bb + o)     : 0.f;
                float v1 = (o + 1 < DOUT) ? a1 + __ldg(bs + o + 1) + __ldg(bb + o + 1) : 0.f;
                *(float2*)(out_t + (size_t)r * OUTS + o) = make_float2(v0, v1);
            }
        }
    }
}

// ---------------- CSR gather aggregation ----------------
__global__ void __launch_bounds__(256)
gat128(const float* __restrict__ tin, const int* __restrict__ rowptr,
       const int* __restrict__ col, const float* __restrict__ wv,
       const float* __restrict__ dinv, const float* __restrict__ bg,
       float* __restrict__ out, int n) {
    int wrp = (blockIdx.x * blockDim.x + threadIdx.x) >> 5;
    int lane = threadIdx.x & 31;
    if (wrp >= n) return;
    int beg = __ldg(rowptr + wrp), end = __ldg(rowptr + wrp + 1);
    float dv = __ldg(dinv + wrp);
    float d2 = dv * dv;
    float4 acc = __ldg((const float4*)(tin + (size_t)wrp * 128) + lane);
    float4 bgv = __ldg((const float4*)bg + lane);
    acc.x = acc.x * d2 + bgv.x;
    acc.y = acc.y * d2 + bgv.y;
    acc.z = acc.z * d2 + bgv.z;
    acc.w = acc.w * d2 + bgv.w;
    for (int e0 = beg; e0 < end; e0 += 32) {
        int e = e0 + lane;
        int s = 0; float wt = 0.f;
        if (e < end) { s = __ldg(col + e); wt = __ldg(wv + e); }
        int m = min(32, end - e0);
        int j = 0;
        for (; j + 4 <= m; j += 4) {
            int s0 = __shfl_sync(0xffffffffu, s, j + 0);
            int s1 = __shfl_sync(0xffffffffu, s, j + 1);
            int s2 = __shfl_sync(0xffffffffu, s, j + 2);
            int s3 = __shfl_sync(0xffffffffu, s, j + 3);
            float w0 = __shfl_sync(0xffffffffu, wt, j + 0);
            float w1 = __shfl_sync(0xffffffffu, wt, j + 1);
            float w2 = __shfl_sync(0xffffffffu, wt, j + 2);
            float w3 = __shfl_sync(0xffffffffu, wt, j + 3);
            float4 v0 = __ldg((const float4*)(tin + (size_t)s0 * 128) + lane);
            float4 v1 = __ldg((const float4*)(tin + (size_t)s1 * 128) + lane);
            float4 v2 = __ldg((const float4*)(tin + (size_t)s2 * 128) + lane);
            float4 v3 = __ldg((const float4*)(tin + (size_t)s3 * 128) + lane);
            acc.x += v0.x * w0 + v1.x * w1 + v2.x * w2 + v3.x * w3;
            acc.y += v0.y * w0 + v1.y * w1 + v2.y * w2 + v3.y * w3;
            acc.z += v0.z * w0 + v1.z * w1 + v2.z * w2 + v3.z * w3;
            acc.w += v0.w * w0 + v1.w * w1 + v2.w * w2 + v3.w * w3;
        }
        for (; j < m; j++) {
            int sj = __shfl_sync(0xffffffffu, s, j);
            float wj = __shfl_sync(0xffffffffu, wt, j);
            float4 v = __ldg((const float4*)(tin + (size_t)sj * 128) + lane);
            acc.x += v.x * wj; acc.y += v.y * wj;
            acc.z += v.z * wj; acc.w += v.w * wj;
        }
    }
    ((float4*)(out + (size_t)wrp * 128))[lane] = acc;
}

// padded-48 input -> width-47 output
__global__ void __launch_bounds__(256)
gat48(const float* __restrict__ tin, const int* __restrict__ rowptr,
      const int* __restrict__ col, const float* __restrict__ wv,
      const float* __restrict__ dinv, const float* __restrict__ bg,
      float* __restrict__ out, int n) {
    int wrp = (blockIdx.x * blockDim.x + threadIdx.x) >> 5;
    int lane = threadIdx.x & 31;
    if (wrp >= n) return;
    int beg = __ldg(rowptr + wrp), end = __ldg(rowptr + wrp + 1);
    float dv = __ldg(dinv + wrp);
    float d2 = dv * dv;
    float4 acc = make_float4(0.f, 0.f, 0.f, 0.f);
    if (lane < 12) {
        acc = __ldg((const float4*)(tin + (size_t)wrp * 48) + lane);
        acc.x *= d2; acc.y *= d2; acc.z *= d2; acc.w *= d2;
        int f = lane * 4;
        acc.x += __ldg(bg + f);
        acc.y += (f + 1 < 47) ? __ldg(bg + f + 1) : 0.f;
        acc.z += (f + 2 < 47) ? __ldg(bg + f + 2) : 0.f;
        acc.w += (f + 3 < 47) ? __ldg(bg + f + 3) : 0.f;
    }
    for (int e0 = beg; e0 < end; e0 += 32) {
        int e = e0 + lane;
        int s = 0; float wt = 0.f;
        if (e < end) { s = __ldg(col + e); wt = __ldg(wv + e); }
        int m = min(32, end - e0);
        int j = 0;
        for (; j + 2 <= m; j += 2) {
            int s0 = __shfl_sync(0xffffffffu, s, j + 0);
            int s1 = __shfl_sync(0xffffffffu, s, j + 1);
            float w0 = __shfl_sync(0xffffffffu, wt, j + 0);
            float w1 = __shfl_sync(0xffffffffu, wt, j + 1);
            if (lane < 12) {
                float4 v0 = __ldg((const float4*)(tin + (size_t)s0 * 48) + lane);
                float4 v1 = __ldg((const float4*)(tin + (size_t)s1 * 48) + lane);
                acc.x += v0.x * w0 + v1.x * w1;
                acc.y += v0.y * w0 + v1.y * w1;
                acc.z += v0.z * w0 + v1.z * w1;
                acc.w += v0.w * w0 + v1.w * w1;
            }
        }
        for (; j < m; j++) {
            int sj = __shfl_sync(0xffffffffu, s, j);
            float wj = __shfl_sync(0xffffffffu, wt, j);
            if (lane < 12) {
                float4 v = __ldg((const float4*)(tin + (size_t)sj * 48) + lane);
                acc.x += v.x * wj; acc.y += v.y * wj;
                acc.z += v.z * wj; acc.w += v.w * wj;
            }
        }
    }
    if (lane < 12) {
        int f = lane * 4;
        float* o = out + (size_t)wrp * 47;
        o[f] = acc.x;
        if (f + 1 < 47) o[f + 1] = acc.y;
        if (f + 2 < 47) o[f + 2] = acc.z;
        if (f + 3 < 47) o[f + 3] = acc.w;
    }
}

// ---------------- launch ----------------
extern "C" void kernel_launch(void* const* d_in, const int* in_sizes, int n_in,
                              void* d_out, int out_size) {
    const float* x  = (const float*)d_in[0];
    const int*   ei = (const int*)d_in[1];
    const int N = in_sizes[0] / FEAT;
    const int E = in_sizes[1] / 2;
    const int* e_src = ei;
    const int* e_dst = ei + E;

    const float* P[21];
    for (int i = 0; i < 21; i++) P[i] = (const float*)d_in[2 + i];

    float *t, *h1, *h2, *wvp, *dinv;
    int *counts, *psum, *bsum, *boff, *rowptr, *cursor, *colp;
    __nv_bfloat16 *w0hi, *w0lo, *w1hi, *w1lo, *w2hi, *w2lo;
    cudaGetSymbolAddress((void**)&t,      g_t);
    cudaGetSymbolAddress((void**)&h1,     g_h1);
    cudaGetSymbolAddress((void**)&h2,     g_h2);
    cudaGetSymbolAddress((void**)&counts, g_counts);
    cudaGetSymbolAddress((void**)&psum,   g_psum);
    cudaGetSymbolAddress((void**)&bsum,   g_bsum);
    cudaGetSymbolAddress((void**)&boff,   g_boff);
    cudaGetSymbolAddress((void**)&rowptr, g_rowptr);
    cudaGetSymbolAddress((void**)&cursor, g_cursor);
    cudaGetSymbolAddress((void**)&colp,   g_col);
    cudaGetSymbolAddress((void**)&wvp,    g_wv);
    cudaGetSymbolAddress((void**)&dinv,   g_dinv);
    cudaGetSymbolAddress((void**)&w0hi, g_w0hi);
    cudaGetSymbolAddress((void**)&w0lo, g_w0lo);
    cudaGetSymbolAddress((void**)&w1hi, g_w1hi);
    cudaGetSymbolAddress((void**)&w1lo, g_w1lo);
    cudaGetSymbolAddress((void**)&w2hi, g_w2hi);
    cudaGetSymbolAddress((void**)&w2lo, g_w2lo);
    float* out = (float*)d_out;

    // lazy side-stream + events (created on first, uncaptured, correctness call)
    static cudaStream_t s2 = nullptr;
    static cudaEvent_t evFork = nullptr, evJoin = nullptr;
    if (!s2) {
        cudaStreamCreateWithFlags(&s2, cudaStreamNonBlocking);
        cudaEventCreateWithFlags(&evFork, cudaEventDisableTiming);
        cudaEventCreateWithFlags(&evJoin, cudaEventDisableTiming);
    }

    const int SM01 = 2 * 128 * 144 + 4 * 128 * 144;  // A(36864) + 2x W dbl (73728) = 110592
    const int SM2  = 2 * 128 * 144 + 4 * 64 * 144;   // 36864 + 36864 = 73728
    cudaFuncSetAttribute(fkan4<128, 128, 128, 128>,
                         cudaFuncAttributeMaxDynamicSharedMemorySize, SM01);
    cudaFuncSetAttribute(fkan4<384, 47, 64, 48>,
                         cudaFuncAttributeMaxDynamicSharedMemorySize, SM2);

    const int GB = (N + 127) / 128;
    const int GW = ((size_t)N * 32 + 255) / 256;
    const int NB = (N + 1023) / 1024;

    // ---- fork: CSR build on side stream, overlapping wt_split + fkan0 ----
    cudaEventRecord(evFork, 0);
    cudaStreamWaitEvent(s2, evFork, 0);
    zero_counts<<<(N + 255) / 256, 256, 0, s2>>>(counts, N);
    hist_kernel<<<(E + 255) / 256, 256, 0, s2>>>(e_dst, counts, E);
    scan_partial<<<NB, 1024, 0, s2>>>(counts, psum, bsum, N);
    scan_tops<<<1, 128, 0, s2>>>(bsum, boff, NB);
    scan_final<<<(N + 256) / 256, 256, 0, s2>>>(psum, boff, counts, rowptr, cursor, dinv, N, E);
    scatter_kernel<<<(E + 255) / 256, 256, 0, s2>>>(e_src, e_dst, dinv, cursor, colp, wvp, E);
    cudaEventRecord(evJoin, s2);

    // ---- main stream: weight prep + layer-0 FKAN ----
    wt_split<<<(640 * 128 + 255) / 256, 256>>>(P[2],  P[4],  w0hi, w0lo, 128, 128, 128);
    wt_split<<<(640 * 128 + 255) / 256, 256>>>(P[9],  P[11], w1hi, w1lo, 128, 128, 128);
    wt_split<<<(1920 * 64 + 255) / 256, 256>>>(P[16], P[18], w2hi, w2lo, 384, 47, 64);
    fkan4<128, 128, 128, 128><<<GB, 256, SM01>>>(
        x, nullptr, nullptr, P[0], P[1], w0hi, w0lo, P[3], P[5], t, N);

    // ---- join: gathers need the CSR ----
    cudaStreamWaitEvent(0, evJoin, 0);
    gat128<<<GW, 256>>>(t, rowptr, colp, wvp, dinv, P[6], h1, N);

    // ---- layer 1
    fkan4<128, 128, 128, 128><<<GB, 256, SM01>>>(
        h1, nullptr, nullptr, P[7], P[8], w1hi, w1lo, P[10], P[12], t, N);
    gat128<<<GW, 256>>>(t, rowptr, colp, wvp, dinv, P[13], h2, N);

    // ---- layer 2 (concat input, padded out width 48 -> final 47)
    fkan4<384, 47, 64, 48><<<GB, 256, SM2>>>(
        x, h1, h2, P[14], P[15], w2hi, w2lo, P[17], P[19], t, N);
    gat48<<<GW, 256>>>(t, rowptr, colp, wvp, dinv, P[20], out, N);
}